// round 1
// baseline (speedup 1.0000x reference)
#include <cuda_runtime.h>
#include <math.h>

namespace {

constexpr int Bc = 8, Sc = 1024, Ec = 768, Hc = 12, Pc = 64, HPc = 768;

// Scratch (no cudaMalloc allowed): ~100 MB total
__device__ float g_k[Bc * Hc * Sc * Pc];
__device__ float g_v[Bc * Hc * Sc * Pc];
__device__ float g_qv[Bc * Hc * Sc * Pc];
__device__ float g_attn[Bc * Sc * HPc];

// ---------------------------------------------------------------------------
// Kernel A: k = x @ key_proj, v = x @ value_proj (fused, N=128 = 64k|64v)
// grid (S/128, H, B), 256 threads, tile 128x128, K-step 16
// ---------------------------------------------------------------------------
__global__ __launch_bounds__(256)
void proj_kernel(const float* __restrict__ x,
                 const float* __restrict__ kp,
                 const float* __restrict__ vp) {
    __shared__ float xs[16][132];
    __shared__ float ws[16][132];
    const int s0 = blockIdx.x * 128;
    const int h = blockIdx.y, b = blockIdx.z;
    const int tid = threadIdx.x;
    const int ty = tid >> 4, tx = tid & 15;
    const float* xb  = x  + (size_t)b * Sc * Ec;
    const float* kph = kp + (size_t)h * Ec * Pc;
    const float* vph = vp + (size_t)h * Ec * Pc;

    float acc[8][8];
#pragma unroll
    for (int u = 0; u < 8; u++)
#pragma unroll
        for (int w = 0; w < 8; w++) acc[u][w] = 0.f;

    for (int k0 = 0; k0 < Ec; k0 += 16) {
#pragma unroll
        for (int i = tid; i < 128 * 16; i += 256) {
            int r = i >> 4, e = i & 15;
            xs[e][r] = xb[(s0 + r) * Ec + k0 + e];
        }
#pragma unroll
        for (int i = tid; i < 16 * 128; i += 256) {
            int e = i >> 7, p = i & 127;
            ws[e][p] = (p < 64) ? kph[(k0 + e) * Pc + p]
                                : vph[(k0 + e) * Pc + (p - 64)];
        }
        __syncthreads();
#pragma unroll
        for (int kk = 0; kk < 16; kk++) {
            float a[8], bb[8];
            *(float4*)(a)      = *(const float4*)&xs[kk][ty * 8];
            *(float4*)(a + 4)  = *(const float4*)&xs[kk][ty * 8 + 4];
            *(float4*)(bb)     = *(const float4*)&ws[kk][tx * 8];
            *(float4*)(bb + 4) = *(const float4*)&ws[kk][tx * 8 + 4];
#pragma unroll
            for (int u = 0; u < 8; u++)
#pragma unroll
                for (int w = 0; w < 8; w++)
                    acc[u][w] = fmaf(a[u], bb[w], acc[u][w]);
        }
        __syncthreads();
    }
    float* kd = g_k + (size_t)(b * Hc + h) * Sc * Pc;
    float* vd = g_v + (size_t)(b * Hc + h) * Sc * Pc;
#pragma unroll
    for (int u = 0; u < 8; u++) {
        int s = s0 + ty * 8 + u;
#pragma unroll
        for (int w = 0; w < 8; w++) {
            int p = tx * 8 + w;
            if (p < 64) kd[s * Pc + p]        = acc[u][w];
            else        vd[s * Pc + (p - 64)] = acc[u][w];
        }
    }
}

// ---------------------------------------------------------------------------
// Kernel B: qv[b,h] = q_heads[h] (SxS) @ v[b,h] (SxP)
// grid (S/128, H, B), 256 threads, tile 128x64, K-step 16
// ---------------------------------------------------------------------------
__global__ __launch_bounds__(256)
void qv_kernel(const float* __restrict__ q) {
    __shared__ float qs[16][132];
    __shared__ float vs[16][68];
    const int m0 = blockIdx.x * 128;
    const int h = blockIdx.y, b = blockIdx.z;
    const int tid = threadIdx.x;
    const int ty = tid >> 4, tx = tid & 15;
    const float* qh = q + (size_t)h * Sc * Sc;
    const float* vb = g_v + (size_t)(b * Hc + h) * Sc * Pc;

    float acc[8][4];
#pragma unroll
    for (int u = 0; u < 8; u++)
#pragma unroll
        for (int w = 0; w < 4; w++) acc[u][w] = 0.f;

    for (int k0 = 0; k0 < Sc; k0 += 16) {
#pragma unroll
        for (int i = tid; i < 128 * 16; i += 256) {
            int r = i >> 4, kk = i & 15;
            qs[kk][r] = qh[(m0 + r) * Sc + k0 + kk];
        }
#pragma unroll
        for (int i = tid; i < 16 * 64; i += 256) {
            int kk = i >> 6, p = i & 63;
            vs[kk][p] = vb[(k0 + kk) * Pc + p];
        }
        __syncthreads();
#pragma unroll
        for (int kk = 0; kk < 16; kk++) {
            float a[8], bb[4];
            *(float4*)(a)     = *(const float4*)&qs[kk][ty * 8];
            *(float4*)(a + 4) = *(const float4*)&qs[kk][ty * 8 + 4];
            *(float4*)(bb)    = *(const float4*)&vs[kk][tx * 4];
#pragma unroll
            for (int u = 0; u < 8; u++)
#pragma unroll
                for (int w = 0; w < 4; w++)
                    acc[u][w] = fmaf(a[u], bb[w], acc[u][w]);
        }
        __syncthreads();
    }
    float* qvd = g_qv + (size_t)(b * Hc + h) * Sc * Pc;
#pragma unroll
    for (int u = 0; u < 8; u++)
#pragma unroll
        for (int w = 0; w < 4; w++)
            qvd[(m0 + ty * 8 + u) * Pc + tx * 4 + w] = acc[u][w];
}

// ---------------------------------------------------------------------------
// Kernel C: causal flash attention with Q = k/sqrt(E), K = qv, V = v.
// attn[b,h,i,:] = softmax_{j<=i}(k[i]·qv[j]/sqrt(E)) @ v
// Output written as (B, S, H*P) for the lift GEMM.
// grid (S/128, H, B), 256 threads. Dynamic smem ~168 KB.
// ---------------------------------------------------------------------------
constexpr int KSTR = 68;
constexpr int PSTR = 132;
constexpr int SMEM_FLASH = (3 * 128 * KSTR + 128 * PSTR) * (int)sizeof(float);

__global__ __launch_bounds__(256)
void flash_kernel() {
    extern __shared__ float sm[];
    float (*Qs)[KSTR] = (float(*)[KSTR])(sm);
    float (*Ks)[KSTR] = (float(*)[KSTR])(sm + 128 * KSTR);
    float (*Vs)[KSTR] = (float(*)[KSTR])(sm + 2 * 128 * KSTR);
    float (*Ps)[PSTR] = (float(*)[PSTR])(sm + 3 * 128 * KSTR);

    const int i0 = blockIdx.x * 128;
    const int h = blockIdx.y, b = blockIdx.z;
    const int tid = threadIdx.x;
    const int ty = tid >> 4, tx = tid & 15;
    const size_t base = (size_t)(b * Hc + h) * Sc * Pc;
    const float* kb  = g_k  + base;
    const float* qvb = g_qv + base;
    const float* vb  = g_v  + base;
    const float qscale = rsqrtf((float)Ec);

#pragma unroll
    for (int i = tid; i < 128 * 64; i += 256) {
        int r = i >> 6, p = i & 63;
        Qs[r][p] = kb[(i0 + r) * Pc + p] * qscale;
    }

    float m[8], l[8], o[8][4];
#pragma unroll
    for (int u = 0; u < 8; u++) {
        m[u] = -INFINITY; l[u] = 0.f;
#pragma unroll
        for (int w = 0; w < 4; w++) o[u][w] = 0.f;
    }

    for (int j0 = 0; j0 <= i0; j0 += 128) {
#pragma unroll
        for (int i = tid; i < 128 * 64; i += 256) {
            int r = i >> 6, p = i & 63;
            Ks[r][p] = qvb[(j0 + r) * Pc + p];
            Vs[r][p] = vb[(j0 + r) * Pc + p];
        }
        __syncthreads();

        // S-tile: rows ty*8+u, cols tx + 16*w (interleaved -> few bank conflicts)
        float s[8][8];
#pragma unroll
        for (int u = 0; u < 8; u++)
#pragma unroll
            for (int w = 0; w < 8; w++) s[u][w] = 0.f;

#pragma unroll 4
        for (int p = 0; p < 64; p++) {
            float a[8], bb[8];
#pragma unroll
            for (int u = 0; u < 8; u++) a[u] = Qs[ty * 8 + u][p];
#pragma unroll
            for (int w = 0; w < 8; w++) bb[w] = Ks[tx + 16 * w][p];
#pragma unroll
            for (int u = 0; u < 8; u++)
#pragma unroll
                for (int w = 0; w < 8; w++)
                    s[u][w] = fmaf(a[u], bb[w], s[u][w]);
        }

        if (j0 == i0) {  // only the diagonal block needs masking
#pragma unroll
            for (int u = 0; u < 8; u++)
#pragma unroll
                for (int w = 0; w < 8; w++)
                    if (tx + 16 * w > ty * 8 + u) s[u][w] = -INFINITY;
        }

        // online softmax update (16-lane shuffle reductions; lanes with same
        // ty form an aligned 16-lane group within the warp)
#pragma unroll
        for (int u = 0; u < 8; u++) {
            float mx = m[u];
#pragma unroll
            for (int w = 0; w < 8; w++) mx = fmaxf(mx, s[u][w]);
#pragma unroll
            for (int off = 8; off >= 1; off >>= 1)
                mx = fmaxf(mx, __shfl_xor_sync(0xffffffffu, mx, off));
            float alpha = __expf(m[u] - mx);
            m[u] = mx;
            float sum = 0.f;
#pragma unroll
            for (int w = 0; w < 8; w++) {
                float pv = __expf(s[u][w] - mx);
                Ps[ty * 8 + u][tx + 16 * w] = pv;
                sum += pv;
            }
#pragma unroll
            for (int off = 8; off >= 1; off >>= 1)
                sum += __shfl_xor_sync(0xffffffffu, sum, off);
            l[u] = l[u] * alpha + sum;
#pragma unroll
            for (int w = 0; w < 4; w++) o[u][w] *= alpha;
        }
        __syncthreads();

        // O-tile: rows ty*8+u, cols tx*4+w
#pragma unroll 4
        for (int jj = 0; jj < 128; jj++) {
            float vv[4];
            *(float4*)vv = *(const float4*)&Vs[jj][tx * 4];
#pragma unroll
            for (int u = 0; u < 8; u++) {
                float pp = Ps[ty * 8 + u][jj];
#pragma unroll
                for (int w = 0; w < 4; w++)
                    o[u][w] = fmaf(pp, vv[w], o[u][w]);
            }
        }
        __syncthreads();
    }

#pragma unroll
    for (int u = 0; u < 8; u++) {
        float inv = 1.f / l[u];
        int row = i0 + ty * 8 + u;
        float* dst = g_attn + ((size_t)b * Sc + row) * HPc + h * Pc + tx * 4;
#pragma unroll
        for (int w = 0; w < 4; w++) dst[w] = o[u][w] * inv;
    }
}

// ---------------------------------------------------------------------------
// Kernel D: out = attn (B*S x HP) @ lifting (HP x E)
// grid (B*S/128, E/128), 256 threads, tile 128x128
// ---------------------------------------------------------------------------
__global__ __launch_bounds__(256)
void lift_kernel(const float* __restrict__ lw, float* __restrict__ out) {
    __shared__ float as_[16][132];
    __shared__ float ws[16][132];
    const int m0 = blockIdx.x * 128;
    const int n0 = blockIdx.y * 128;
    const int tid = threadIdx.x;
    const int ty = tid >> 4, tx = tid & 15;

    float acc[8][8];
#pragma unroll
    for (int u = 0; u < 8; u++)
#pragma unroll
        for (int w = 0; w < 8; w++) acc[u][w] = 0.f;

    for (int k0 = 0; k0 < HPc; k0 += 16) {
#pragma unroll
        for (int i = tid; i < 128 * 16; i += 256) {
            int r = i >> 4, e = i & 15;
            as_[e][r] = g_attn[(size_t)(m0 + r) * HPc + k0 + e];
        }
#pragma unroll
        for (int i = tid; i < 16 * 128; i += 256) {
            int e = i >> 7, n = i & 127;
            ws[e][n] = lw[(size_t)(k0 + e) * Ec + n0 + n];
        }
        __syncthreads();
#pragma unroll
        for (int kk = 0; kk < 16; kk++) {
            float a[8], bb[8];
            *(float4*)(a)      = *(const float4*)&as_[kk][ty * 8];
            *(float4*)(a + 4)  = *(const float4*)&as_[kk][ty * 8 + 4];
            *(float4*)(bb)     = *(const float4*)&ws[kk][tx * 8];
            *(float4*)(bb + 4) = *(const float4*)&ws[kk][tx * 8 + 4];
#pragma unroll
            for (int u = 0; u < 8; u++)
#pragma unroll
                for (int w = 0; w < 8; w++)
                    acc[u][w] = fmaf(a[u], bb[w], acc[u][w]);
        }
        __syncthreads();
    }
#pragma unroll
    for (int u = 0; u < 8; u++)
#pragma unroll
        for (int w = 0; w < 8; w++)
            out[(size_t)(m0 + ty * 8 + u) * Ec + n0 + tx * 8 + w] = acc[u][w];
}

}  // namespace

extern "C" void kernel_launch(void* const* d_in, const int* in_sizes, int n_in,
                              void* d_out, int out_size) {
    (void)in_sizes; (void)n_in; (void)out_size;
    const float* x  = (const float*)d_in[0];   // (B,1,S,E)
    const float* kp = (const float*)d_in[1];   // (H,E,P)
    const float* vp = (const float*)d_in[2];   // (H,E,P)
    const float* qh = (const float*)d_in[3];   // (H,S,S)
    const float* lw = (const float*)d_in[4];   // (1,HP,E)
    float* out = (float*)d_out;                // (B,S,E)

    // Idempotent, deterministic; not a stream op so capture-safe.
    cudaFuncSetAttribute(flash_kernel,
                         cudaFuncAttributeMaxDynamicSharedMemorySize, SMEM_FLASH);

    proj_kernel<<<dim3(Sc / 128, Hc, Bc), 256>>>(x, kp, vp);
    qv_kernel<<<dim3(Sc / 128, Hc, Bc), 256>>>(qh);
    flash_kernel<<<dim3(Sc / 128, Hc, Bc), 256, SMEM_FLASH>>>();
    lift_kernel<<<dim3(Bc * Sc / 128, Ec / 128), 256>>>(lw, out);
}

// round 3
// speedup vs baseline: 1.6299x; 1.6299x over previous
#include <cuda_runtime.h>
#include <math.h>
#include <stdint.h>

namespace {

constexpr int Bc = 8, Sc = 1024, Ec = 768, Hc = 12, Pc = 64, HPc = 768;

// Scratch (no cudaMalloc allowed): ~100 MB total
__device__ float g_k[Bc * Hc * Sc * Pc];
__device__ float g_v[Bc * Hc * Sc * Pc];
__device__ float g_qv[Bc * Hc * Sc * Pc];
__device__ float g_attn[Bc * Sc * HPc];

__device__ __forceinline__ float to_tf32(float x) {
    float y;
    asm("cvt.rna.tf32.f32 %0, %1;" : "=f"(y) : "f"(x));
    return y;
}

__device__ __forceinline__ void mma_tf32(float c[4], const uint32_t a[4],
                                         const uint32_t b[2]) {
    asm volatile(
        "mma.sync.aligned.m16n8k8.row.col.f32.tf32.tf32.f32 "
        "{%0,%1,%2,%3}, {%4,%5,%6,%7}, {%8,%9}, {%0,%1,%2,%3};"
        : "+f"(c[0]), "+f"(c[1]), "+f"(c[2]), "+f"(c[3])
        : "r"(a[0]), "r"(a[1]), "r"(a[2]), "r"(a[3]), "r"(b[0]), "r"(b[1]));
}

// ---------------------------------------------------------------------------
// tf32 mma.sync GEMM: C[128 x NT] block tile = A[128 x K] * B[K x NT]
// MODE 0: proj (A=x[b], B=concat(kp[h],vp[h]) 768x128, out split g_k|g_v)
// MODE 1: qv   (A=q_heads[h], B=g_v[b,h], NT=64, out g_qv)
// MODE 2: lift (A=g_attn, B=lifting[:, n0:n0+128], out d_out)
// smem layout: As[k][m] stride 136, Bs[k][n] stride NT+8  (both ≡ 8 mod 32
// floats → fragment loads are bank-conflict-free permutations of 0..31)
// ---------------------------------------------------------------------------
template <int NT, int MODE>
__global__ __launch_bounds__(256)
void mma_gemm(const float* __restrict__ P0, const float* __restrict__ P1,
              const float* __restrict__ P2, float* __restrict__ Out) {
    constexpr int WR = (NT == 128) ? 2 : 4;   // warp rows
    constexpr int WC = (NT == 128) ? 4 : 2;   // warp cols
    constexpr int WM = 128 / WR;              // 64 or 32
    constexpr int WN = NT / WC;               // 32
    constexpr int MT = WM / 16;               // m16 tiles per warp
    constexpr int NTT = WN / 8;               // n8 tiles per warp
    constexpr int ASTR = 136;                 // 128 + 8
    constexpr int BSTR = NT + 8;

    __shared__ float As[16][ASTR];
    __shared__ float Bs[16][BSTR];

    const int tid = threadIdx.x;
    const int wid = tid >> 5, lane = tid & 31;
    const int wr = (NT == 128) ? (wid >> 2) : (wid >> 1);
    const int wc = (NT == 128) ? (wid & 3) : (wid & 1);
    const int wm0 = wr * WM, wn0 = wc * WN;
    const int qk = lane & 3, qr = lane >> 2;   // frag row/col pieces

    const int row0 = blockIdx.x * 128;
    const int hy = blockIdx.y, bz = blockIdx.z;

    const float* A;
    int lda, K;
    const float* Bp = nullptr;
    int ldb = 0;
    const float* kph = nullptr;
    const float* vph = nullptr;
    int n0g = 0;
    if (MODE == 0) {
        A = P0 + (size_t)bz * Sc * Ec; lda = Ec; K = Ec;
        kph = P1 + (size_t)hy * Ec * Pc;
        vph = P2 + (size_t)hy * Ec * Pc;
    } else if (MODE == 1) {
        A = P0 + (size_t)hy * Sc * Sc; lda = Sc; K = Sc;
        Bp = g_v + (size_t)(bz * Hc + hy) * Sc * Pc; ldb = Pc;
    } else {
        A = g_attn; lda = HPc; K = HPc;
        n0g = blockIdx.y * 128;
        Bp = P0 + n0g; ldb = Ec;
    }

    float c[MT][NTT][4];
#pragma unroll
    for (int mt = 0; mt < MT; mt++)
#pragma unroll
        for (int nt = 0; nt < NTT; nt++)
#pragma unroll
            for (int q = 0; q < 4; q++) c[mt][nt][q] = 0.f;

    for (int k0 = 0; k0 < K; k0 += 16) {
        // fill A: As[e][r] = tf32(A[row0+r][k0+e])
#pragma unroll
        for (int i = tid; i < 128 * 16; i += 256) {
            int r = i >> 4, e = i & 15;
            As[e][r] = to_tf32(A[(size_t)(row0 + r) * lda + k0 + e]);
        }
        // fill B: Bs[kk][n] = tf32(B[k0+kk][n])
#pragma unroll
        for (int i = tid; i < 16 * NT; i += 256) {
            int kk = i / NT, n = i % NT;
            float val;
            if (MODE == 0)
                val = (n < 64) ? kph[(size_t)(k0 + kk) * Pc + n]
                               : vph[(size_t)(k0 + kk) * Pc + (n - 64)];
            else
                val = Bp[(size_t)(k0 + kk) * ldb + n];
            Bs[kk][n] = to_tf32(val);
        }
        __syncthreads();

#pragma unroll
        for (int kk8 = 0; kk8 < 16; kk8 += 8) {
            uint32_t a[MT][4], b[NTT][2];
#pragma unroll
            for (int mt = 0; mt < MT; mt++) {
                int m0 = wm0 + mt * 16;
                a[mt][0] = __float_as_uint(As[kk8 + qk][m0 + qr]);
                a[mt][1] = __float_as_uint(As[kk8 + qk][m0 + qr + 8]);
                a[mt][2] = __float_as_uint(As[kk8 + qk + 4][m0 + qr]);
                a[mt][3] = __float_as_uint(As[kk8 + qk + 4][m0 + qr + 8]);
            }
#pragma unroll
            for (int nt = 0; nt < NTT; nt++) {
                int n0 = wn0 + nt * 8;
                b[nt][0] = __float_as_uint(Bs[kk8 + qk][n0 + qr]);
                b[nt][1] = __float_as_uint(Bs[kk8 + qk + 4][n0 + qr]);
            }
#pragma unroll
            for (int mt = 0; mt < MT; mt++)
#pragma unroll
                for (int nt = 0; nt < NTT; nt++)
                    mma_tf32(c[mt][nt], a[mt], b[nt]);
        }
        __syncthreads();
    }

    // epilogue: c0,c1 -> (row, col..col+1); c2,c3 -> (row+8, col..col+1)
#pragma unroll
    for (int mt = 0; mt < MT; mt++) {
#pragma unroll
        for (int nt = 0; nt < NTT; nt++) {
            int row = row0 + wm0 + mt * 16 + qr;
            int col = wn0 + nt * 8 + 2 * qk;
            float2 lo = make_float2(c[mt][nt][0], c[mt][nt][1]);
            float2 hi = make_float2(c[mt][nt][2], c[mt][nt][3]);
            if (MODE == 0) {
                float* base = ((col < 64) ? g_k : g_v) +
                              (size_t)(bz * Hc + hy) * Sc * Pc;
                int cc = col & 63;
                *(float2*)(base + (size_t)row * Pc + cc) = lo;
                *(float2*)(base + (size_t)(row + 8) * Pc + cc) = hi;
            } else if (MODE == 1) {
                float* base = g_qv + (size_t)(bz * Hc + hy) * Sc * Pc;
                *(float2*)(base + (size_t)row * Pc + col) = lo;
                *(float2*)(base + (size_t)(row + 8) * Pc + col) = hi;
            } else {
                *(float2*)(Out + (size_t)row * Ec + n0g + col) = lo;
                *(float2*)(Out + (size_t)(row + 8) * Ec + n0g + col) = hi;
            }
        }
    }
}

// ---------------------------------------------------------------------------
// Kernel C: causal flash attention with Q = k/sqrt(E), K = qv, V = v (fp32)
// ---------------------------------------------------------------------------
constexpr int KSTR = 68;
constexpr int PSTR = 132;
constexpr int SMEM_FLASH = (3 * 128 * KSTR + 128 * PSTR) * (int)sizeof(float);

__global__ __launch_bounds__(256)
void flash_kernel() {
    extern __shared__ float sm[];
    float (*Qs)[KSTR] = (float(*)[KSTR])(sm);
    float (*Ks)[KSTR] = (float(*)[KSTR])(sm + 128 * KSTR);
    float (*Vs)[KSTR] = (float(*)[KSTR])(sm + 2 * 128 * KSTR);
    float (*Ps)[PSTR] = (float(*)[PSTR])(sm + 3 * 128 * KSTR);

    const int i0 = blockIdx.x * 128;
    const int h = blockIdx.y, b = blockIdx.z;
    const int tid = threadIdx.x;
    const int ty = tid >> 4, tx = tid & 15;
    const size_t base = (size_t)(b * Hc + h) * Sc * Pc;
    const float* kb  = g_k  + base;
    const float* qvb = g_qv + base;
    const float* vb  = g_v  + base;
    const float qscale = rsqrtf((float)Ec);

#pragma unroll
    for (int i = tid; i < 128 * 64; i += 256) {
        int r = i >> 6, p = i & 63;
        Qs[r][p] = kb[(i0 + r) * Pc + p] * qscale;
    }

    float m[8], l[8], o[8][4];
#pragma unroll
    for (int u = 0; u < 8; u++) {
        m[u] = -INFINITY; l[u] = 0.f;
#pragma unroll
        for (int w = 0; w < 4; w++) o[u][w] = 0.f;
    }

    for (int j0 = 0; j0 <= i0; j0 += 128) {
#pragma unroll
        for (int i = tid; i < 128 * 64; i += 256) {
            int r = i >> 6, p = i & 63;
            Ks[r][p] = qvb[(j0 + r) * Pc + p];
            Vs[r][p] = vb[(j0 + r) * Pc + p];
        }
        __syncthreads();

        float s[8][8];
#pragma unroll
        for (int u = 0; u < 8; u++)
#pragma unroll
            for (int w = 0; w < 8; w++) s[u][w] = 0.f;

#pragma unroll 4
        for (int p = 0; p < 64; p++) {
            float a[8], bb[8];
#pragma unroll
            for (int u = 0; u < 8; u++) a[u] = Qs[ty * 8 + u][p];
#pragma unroll
            for (int w = 0; w < 8; w++) bb[w] = Ks[tx + 16 * w][p];
#pragma unroll
            for (int u = 0; u < 8; u++)
#pragma unroll
                for (int w = 0; w < 8; w++)
                    s[u][w] = fmaf(a[u], bb[w], s[u][w]);
        }

        if (j0 == i0) {
#pragma unroll
            for (int u = 0; u < 8; u++)
#pragma unroll
                for (int w = 0; w < 8; w++)
                    if (tx + 16 * w > ty * 8 + u) s[u][w] = -INFINITY;
        }

#pragma unroll
        for (int u = 0; u < 8; u++) {
            float mx = m[u];
#pragma unroll
            for (int w = 0; w < 8; w++) mx = fmaxf(mx, s[u][w]);
#pragma unroll
            for (int off = 8; off >= 1; off >>= 1)
                mx = fmaxf(mx, __shfl_xor_sync(0xffffffffu, mx, off));
            float alpha = __expf(m[u] - mx);
            m[u] = mx;
            float sum = 0.f;
#pragma unroll
            for (int w = 0; w < 8; w++) {
                float pv = __expf(s[u][w] - mx);
                Ps[ty * 8 + u][tx + 16 * w] = pv;
                sum += pv;
            }
#pragma unroll
            for (int off = 8; off >= 1; off >>= 1)
                sum += __shfl_xor_sync(0xffffffffu, sum, off);
            l[u] = l[u] * alpha + sum;
#pragma unroll
            for (int w = 0; w < 4; w++) o[u][w] *= alpha;
        }
        __syncthreads();

#pragma unroll 4
        for (int jj = 0; jj < 128; jj++) {
            float vv[4];
            *(float4*)vv = *(const float4*)&Vs[jj][tx * 4];
#pragma unroll
            for (int u = 0; u < 8; u++) {
                float pp = Ps[ty * 8 + u][jj];
#pragma unroll
                for (int w = 0; w < 4; w++)
                    o[u][w] = fmaf(pp, vv[w], o[u][w]);
            }
        }
        __syncthreads();
    }

#pragma unroll
    for (int u = 0; u < 8; u++) {
        float inv = 1.f / l[u];
        int row = i0 + ty * 8 + u;
        float* dst = g_attn + ((size_t)b * Sc + row) * HPc + h * Pc + tx * 4;
#pragma unroll
        for (int w = 0; w < 4; w++) dst[w] = o[u][w] * inv;
    }
}

}  // namespace

extern "C" void kernel_launch(void* const* d_in, const int* in_sizes, int n_in,
                              void* d_out, int out_size) {
    (void)in_sizes; (void)n_in; (void)out_size;
    const float* x  = (const float*)d_in[0];   // (B,1,S,E)
    const float* kp = (const float*)d_in[1];   // (H,E,P)
    const float* vp = (const float*)d_in[2];   // (H,E,P)
    const float* qh = (const float*)d_in[3];   // (H,S,S)
    const float* lw = (const float*)d_in[4];   // (1,HP,E)
    float* out = (float*)d_out;                // (B,S,E)

    cudaFuncSetAttribute(flash_kernel,
                         cudaFuncAttributeMaxDynamicSharedMemorySize, SMEM_FLASH);

    // proj: k|v = x @ [kp|vp]
    mma_gemm<128, 0><<<dim3(Sc / 128, Hc, Bc), 256>>>(x, kp, vp, nullptr);
    // qv = q_heads @ v
    mma_gemm<64, 1><<<dim3(Sc / 128, Hc, Bc), 256>>>(qh, nullptr, nullptr, nullptr);
    // flash attention (fp32)
    flash_kernel<<<dim3(Sc / 128, Hc, Bc), 256, SMEM_FLASH>>>();
    // out = attn @ lifting
    mma_gemm<128, 2><<<dim3(Bc * Sc / 128, Ec / 128), 256>>>(lw, nullptr, nullptr, out);
}

// round 4
// speedup vs baseline: 2.9533x; 1.8120x over previous
#include <cuda_runtime.h>
#include <math.h>
#include <stdint.h>

namespace {

constexpr int Bc = 8, Sc = 1024, Ec = 768, Hc = 12, Pc = 64, HPc = 768;

__device__ float g_k[Bc * Hc * Sc * Pc];
__device__ float g_v[Bc * Hc * Sc * Pc];
__device__ float g_qv[Bc * Hc * Sc * Pc];
__device__ float g_attn[Bc * Sc * HPc];

__device__ __forceinline__ float to_tf32(float x) {
    float y;
    asm("cvt.rna.tf32.f32 %0, %1;" : "=f"(y) : "f"(x));
    return y;
}

__device__ __forceinline__ void mma_tf32(float c[4], const uint32_t a[4],
                                         const uint32_t b[2]) {
    asm volatile(
        "mma.sync.aligned.m16n8k8.row.col.f32.tf32.tf32.f32 "
        "{%0,%1,%2,%3}, {%4,%5,%6,%7}, {%8,%9}, {%0,%1,%2,%3};"
        : "+f"(c[0]), "+f"(c[1]), "+f"(c[2]), "+f"(c[3])
        : "r"(a[0]), "r"(a[1]), "r"(a[2]), "r"(a[3]), "r"(b[0]), "r"(b[1]));
}

// ---------------------------------------------------------------------------
// tf32 mma.sync GEMM with register-prefetch pipeline.
// A tile: As[m][k] row-major stride 20 (conflict-free frag reads, coalesced fill)
// B tile: Bs[k][n] stride NT+8 (conflict-free both ways)
// MODE 0: proj  MODE 1: qv (NT=64)  MODE 2: lift
// ---------------------------------------------------------------------------
template <int NT, int MODE>
__global__ __launch_bounds__(256)
void mma_gemm(const float* __restrict__ P0, const float* __restrict__ P1,
              const float* __restrict__ P2, float* __restrict__ Out) {
    constexpr int WR = (NT == 128) ? 2 : 4;
    constexpr int WC = (NT == 128) ? 4 : 2;
    constexpr int WM = 128 / WR;
    constexpr int WN = NT / WC;
    constexpr int MT = WM / 16;
    constexpr int NTT = WN / 8;
    constexpr int ASTR = 20;
    constexpr int BSTR = NT + 8;
    constexpr int NB4 = (NT * 16) / (4 * 256);   // float4 B loads per thread

    __shared__ float As[128][ASTR];
    __shared__ float Bs[16][BSTR];

    const int tid = threadIdx.x;
    const int wid = tid >> 5, lane = tid & 31;
    const int wr = (NT == 128) ? (wid >> 2) : (wid >> 1);
    const int wc = (NT == 128) ? (wid & 3) : (wid & 1);
    const int wm0 = wr * WM, wn0 = wc * WN;
    const int qk = lane & 3, qr = lane >> 2;

    const int row0 = blockIdx.x * 128;
    const int hy = blockIdx.y, bz = blockIdx.z;

    const float* A;
    int lda, K;
    const float* Bp = nullptr;
    int ldb = 0;
    const float* kph = nullptr;
    const float* vph = nullptr;
    int n0g = 0;
    if (MODE == 0) {
        A = P0 + (size_t)bz * Sc * Ec; lda = Ec; K = Ec;
        kph = P1 + (size_t)hy * Ec * Pc;
        vph = P2 + (size_t)hy * Ec * Pc;
    } else if (MODE == 1) {
        A = P0 + (size_t)hy * Sc * Sc; lda = Sc; K = Sc;
        Bp = g_v + (size_t)(bz * Hc + hy) * Sc * Pc; ldb = Pc;
    } else {
        A = g_attn; lda = HPc; K = HPc;
        n0g = blockIdx.y * 128;
        Bp = P0 + n0g; ldb = Ec;
    }

    float c[MT][NTT][4];
#pragma unroll
    for (int mt = 0; mt < MT; mt++)
#pragma unroll
        for (int nt = 0; nt < NTT; nt++)
#pragma unroll
            for (int q = 0; q < 4; q++) c[mt][nt][q] = 0.f;

    float4 pa[2], pb[NB4];

    auto loadA = [&](int k0) {
#pragma unroll
        for (int j = 0; j < 2; j++) {
            int i = j * 256 + tid;
            int m = i >> 2, e4 = (i & 3) * 4;
            pa[j] = *(const float4*)(A + (size_t)(row0 + m) * lda + k0 + e4);
        }
    };
    auto loadB = [&](int k0) {
#pragma unroll
        for (int j = 0; j < NB4; j++) {
            int i = j * 256 + tid;
            int kk = (NT == 128) ? (i >> 5) : (i >> 4);
            int n4 = (NT == 128) ? ((i & 31) * 4) : ((i & 15) * 4);
            if (MODE == 0)
                pb[j] = (n4 < 64)
                    ? *(const float4*)(kph + (size_t)(k0 + kk) * Pc + n4)
                    : *(const float4*)(vph + (size_t)(k0 + kk) * Pc + (n4 - 64));
            else
                pb[j] = *(const float4*)(Bp + (size_t)(k0 + kk) * ldb + n4);
        }
    };

    loadA(0);
    loadB(0);

    const int nT = K / 16;
    for (int t = 0; t < nT; t++) {
#pragma unroll
        for (int j = 0; j < 2; j++) {
            int i = j * 256 + tid;
            int m = i >> 2, e4 = (i & 3) * 4;
            As[m][e4 + 0] = to_tf32(pa[j].x);
            As[m][e4 + 1] = to_tf32(pa[j].y);
            As[m][e4 + 2] = to_tf32(pa[j].z);
            As[m][e4 + 3] = to_tf32(pa[j].w);
        }
#pragma unroll
        for (int j = 0; j < NB4; j++) {
            int i = j * 256 + tid;
            int kk = (NT == 128) ? (i >> 5) : (i >> 4);
            int n4 = (NT == 128) ? ((i & 31) * 4) : ((i & 15) * 4);
            Bs[kk][n4 + 0] = to_tf32(pb[j].x);
            Bs[kk][n4 + 1] = to_tf32(pb[j].y);
            Bs[kk][n4 + 2] = to_tf32(pb[j].z);
            Bs[kk][n4 + 3] = to_tf32(pb[j].w);
        }
        __syncthreads();
        if (t + 1 < nT) { loadA((t + 1) * 16); loadB((t + 1) * 16); }

#pragma unroll
        for (int kk8 = 0; kk8 < 16; kk8 += 8) {
            uint32_t a[MT][4], b[NTT][2];
#pragma unroll
            for (int mt = 0; mt < MT; mt++) {
                int m0 = wm0 + mt * 16;
                a[mt][0] = __float_as_uint(As[m0 + qr][kk8 + qk]);
                a[mt][1] = __float_as_uint(As[m0 + qr + 8][kk8 + qk]);
                a[mt][2] = __float_as_uint(As[m0 + qr][kk8 + qk + 4]);
                a[mt][3] = __float_as_uint(As[m0 + qr + 8][kk8 + qk + 4]);
            }
#pragma unroll
            for (int nt = 0; nt < NTT; nt++) {
                int n0 = wn0 + nt * 8;
                b[nt][0] = __float_as_uint(Bs[kk8 + qk][n0 + qr]);
                b[nt][1] = __float_as_uint(Bs[kk8 + qk + 4][n0 + qr]);
            }
#pragma unroll
            for (int mt = 0; mt < MT; mt++)
#pragma unroll
                for (int nt = 0; nt < NTT; nt++)
                    mma_tf32(c[mt][nt], a[mt], b[nt]);
        }
        __syncthreads();
    }

#pragma unroll
    for (int mt = 0; mt < MT; mt++) {
#pragma unroll
        for (int nt = 0; nt < NTT; nt++) {
            int row = row0 + wm0 + mt * 16 + qr;
            int col = wn0 + nt * 8 + 2 * qk;
            float2 lo = make_float2(c[mt][nt][0], c[mt][nt][1]);
            float2 hi = make_float2(c[mt][nt][2], c[mt][nt][3]);
            if (MODE == 0) {
                float* base = ((col < 64) ? g_k : g_v) +
                              (size_t)(bz * Hc + hy) * Sc * Pc;
                int cc = col & 63;
                *(float2*)(base + (size_t)row * Pc + cc) = lo;
                *(float2*)(base + (size_t)(row + 8) * Pc + cc) = hi;
            } else if (MODE == 1) {
                float* base = g_qv + (size_t)(bz * Hc + hy) * Sc * Pc;
                *(float2*)(base + (size_t)row * Pc + col) = lo;
                *(float2*)(base + (size_t)(row + 8) * Pc + col) = hi;
            } else {
                *(float2*)(Out + (size_t)row * Ec + n0g + col) = lo;
                *(float2*)(Out + (size_t)(row + 8) * Ec + n0g + col) = hi;
            }
        }
    }
}

// ---------------------------------------------------------------------------
// Flash attention on mma.sync tf32.  Q = k/sqrt(E), K = qv, V = v.
// Warp tile = 16 rows x full width -> softmax reductions are quad shuffles.
// Qs/Ks row-major stride 68; Vs col-major [k][n] stride 72; Ps [m][k] stride 132.
// ---------------------------------------------------------------------------
constexpr int QSTR = 68, VSTR = 72, PSTRm = 132;
constexpr int SMEM_FLASH =
    (128 * QSTR + 128 * QSTR + 128 * VSTR + 128 * PSTRm) * (int)sizeof(float);

__global__ __launch_bounds__(256)
void flash_mma() {
    extern __shared__ float sm[];
    float (*Qs)[QSTR]  = (float(*)[QSTR])(sm);
    float (*Ks)[QSTR]  = (float(*)[QSTR])(sm + 128 * QSTR);
    float (*Vs)[VSTR]  = (float(*)[VSTR])(sm + 2 * 128 * QSTR);
    float (*Ps)[PSTRm] = (float(*)[PSTRm])(sm + 2 * 128 * QSTR + 128 * VSTR);

    const int i0 = blockIdx.x * 128;
    const int h = blockIdx.y, b = blockIdx.z;
    const int tid = threadIdx.x;
    const int wid = tid >> 5, lane = tid & 31;
    const int qk = lane & 3, qr = lane >> 2;
    const int m0 = wid * 16;

    const size_t base = (size_t)(b * Hc + h) * Sc * Pc;
    const float* kb  = g_k  + base;
    const float* qvb = g_qv + base;
    const float* vb  = g_v  + base;
    const float qscale = rsqrtf((float)Ec);

    // Q tile (scaled, tf32)
#pragma unroll
    for (int i = tid; i < 128 * 16; i += 256) {
        int r = i >> 4, c4 = (i & 15) * 4;
        float4 v = *(const float4*)(kb + (size_t)(i0 + r) * Pc + c4);
        Qs[r][c4 + 0] = to_tf32(v.x * qscale);
        Qs[r][c4 + 1] = to_tf32(v.y * qscale);
        Qs[r][c4 + 2] = to_tf32(v.z * qscale);
        Qs[r][c4 + 3] = to_tf32(v.w * qscale);
    }

    float mrow[2] = {-INFINITY, -INFINITY};
    float lrow[2] = {0.f, 0.f};
    float o[8][4];
#pragma unroll
    for (int nt = 0; nt < 8; nt++)
#pragma unroll
        for (int q = 0; q < 4; q++) o[nt][q] = 0.f;

    for (int j0 = 0; j0 <= i0; j0 += 128) {
        __syncthreads();
#pragma unroll
        for (int i = tid; i < 128 * 16; i += 256) {
            int r = i >> 4, c4 = (i & 15) * 4;
            float4 kv = *(const float4*)(qvb + (size_t)(j0 + r) * Pc + c4);
            Ks[r][c4 + 0] = to_tf32(kv.x);
            Ks[r][c4 + 1] = to_tf32(kv.y);
            Ks[r][c4 + 2] = to_tf32(kv.z);
            Ks[r][c4 + 3] = to_tf32(kv.w);
            float4 vv = *(const float4*)(vb + (size_t)(j0 + r) * Pc + c4);
            Vs[r][c4 + 0] = to_tf32(vv.x);
            Vs[r][c4 + 1] = to_tf32(vv.y);
            Vs[r][c4 + 2] = to_tf32(vv.z);
            Vs[r][c4 + 3] = to_tf32(vv.w);
        }
        __syncthreads();

        // S = Q @ K^T : 16 n-frags, K=64
        float s[16][4];
#pragma unroll
        for (int nt = 0; nt < 16; nt++)
#pragma unroll
            for (int q = 0; q < 4; q++) s[nt][q] = 0.f;

#pragma unroll
        for (int kk8 = 0; kk8 < 64; kk8 += 8) {
            uint32_t a[4];
            a[0] = __float_as_uint(Qs[m0 + qr][kk8 + qk]);
            a[1] = __float_as_uint(Qs[m0 + qr + 8][kk8 + qk]);
            a[2] = __float_as_uint(Qs[m0 + qr][kk8 + qk + 4]);
            a[3] = __float_as_uint(Qs[m0 + qr + 8][kk8 + qk + 4]);
#pragma unroll
            for (int nt = 0; nt < 16; nt++) {
                uint32_t bf[2];
                bf[0] = __float_as_uint(Ks[nt * 8 + qr][kk8 + qk]);
                bf[1] = __float_as_uint(Ks[nt * 8 + qr][kk8 + qk + 4]);
                mma_tf32(s[nt], a, bf);
            }
        }

        if (j0 == i0) {  // causal mask on diagonal block (local indices)
            int r0 = m0 + qr, r1 = r0 + 8;
#pragma unroll
            for (int nt = 0; nt < 16; nt++) {
                int c0 = nt * 8 + 2 * qk;
                if (c0 > r0)     s[nt][0] = -INFINITY;
                if (c0 + 1 > r0) s[nt][1] = -INFINITY;
                if (c0 > r1)     s[nt][2] = -INFINITY;
                if (c0 + 1 > r1) s[nt][3] = -INFINITY;
            }
        }

        // online softmax for the thread's two rows (quad = 4 lanes, same qr)
        float mx0 = mrow[0], mx1 = mrow[1];
#pragma unroll
        for (int nt = 0; nt < 16; nt++) {
            mx0 = fmaxf(mx0, fmaxf(s[nt][0], s[nt][1]));
            mx1 = fmaxf(mx1, fmaxf(s[nt][2], s[nt][3]));
        }
#pragma unroll
        for (int off = 1; off <= 2; off <<= 1) {
            mx0 = fmaxf(mx0, __shfl_xor_sync(0xffffffffu, mx0, off));
            mx1 = fmaxf(mx1, __shfl_xor_sync(0xffffffffu, mx1, off));
        }
        float alpha0 = __expf(mrow[0] - mx0);
        float alpha1 = __expf(mrow[1] - mx1);
        mrow[0] = mx0; mrow[1] = mx1;
        float sum0 = 0.f, sum1 = 0.f;
#pragma unroll
        for (int nt = 0; nt < 16; nt++) {
            int c0 = nt * 8 + 2 * qk;
            float p0 = to_tf32(__expf(s[nt][0] - mx0));
            float p1 = to_tf32(__expf(s[nt][1] - mx0));
            float p2 = to_tf32(__expf(s[nt][2] - mx1));
            float p3 = to_tf32(__expf(s[nt][3] - mx1));
            sum0 += p0 + p1;
            sum1 += p2 + p3;
            *(float2*)&Ps[m0 + qr][c0]     = make_float2(p0, p1);
            *(float2*)&Ps[m0 + qr + 8][c0] = make_float2(p2, p3);
        }
#pragma unroll
        for (int off = 1; off <= 2; off <<= 1) {
            sum0 += __shfl_xor_sync(0xffffffffu, sum0, off);
            sum1 += __shfl_xor_sync(0xffffffffu, sum1, off);
        }
        lrow[0] = lrow[0] * alpha0 + sum0;
        lrow[1] = lrow[1] * alpha1 + sum1;
#pragma unroll
        for (int nt = 0; nt < 8; nt++) {
            o[nt][0] *= alpha0; o[nt][1] *= alpha0;
            o[nt][2] *= alpha1; o[nt][3] *= alpha1;
        }
        __syncwarp();  // Ps rows are warp-private; warp-local visibility enough

        // O += P @ V : K = 128, 8 n-frags
#pragma unroll
        for (int kk8 = 0; kk8 < 128; kk8 += 8) {
            uint32_t a[4];
            a[0] = __float_as_uint(Ps[m0 + qr][kk8 + qk]);
            a[1] = __float_as_uint(Ps[m0 + qr + 8][kk8 + qk]);
            a[2] = __float_as_uint(Ps[m0 + qr][kk8 + qk + 4]);
            a[3] = __float_as_uint(Ps[m0 + qr + 8][kk8 + qk + 4]);
#pragma unroll
            for (int nt = 0; nt < 8; nt++) {
                uint32_t bf[2];
                bf[0] = __float_as_uint(Vs[kk8 + qk][nt * 8 + qr]);
                bf[1] = __float_as_uint(Vs[kk8 + qk + 4][nt * 8 + qr]);
                mma_tf32(o[nt], a, bf);
            }
        }
    }

    float inv0 = 1.f / lrow[0], inv1 = 1.f / lrow[1];
    int r0 = i0 + m0 + qr, r1 = r0 + 8;
    float* d0 = g_attn + ((size_t)b * Sc + r0) * HPc + h * Pc;
    float* d1 = g_attn + ((size_t)b * Sc + r1) * HPc + h * Pc;
#pragma unroll
    for (int nt = 0; nt < 8; nt++) {
        int cc = nt * 8 + 2 * qk;
        *(float2*)(d0 + cc) = make_float2(o[nt][0] * inv0, o[nt][1] * inv0);
        *(float2*)(d1 + cc) = make_float2(o[nt][2] * inv1, o[nt][3] * inv1);
    }
}

}  // namespace

extern "C" void kernel_launch(void* const* d_in, const int* in_sizes, int n_in,
                              void* d_out, int out_size) {
    (void)in_sizes; (void)n_in; (void)out_size;
    const float* x  = (const float*)d_in[0];   // (B,1,S,E)
    const float* kp = (const float*)d_in[1];   // (H,E,P)
    const float* vp = (const float*)d_in[2];   // (H,E,P)
    const float* qh = (const float*)d_in[3];   // (H,S,S)
    const float* lw = (const float*)d_in[4];   // (1,HP,E)
    float* out = (float*)d_out;                // (B,S,E)

    cudaFuncSetAttribute(flash_mma,
                         cudaFuncAttributeMaxDynamicSharedMemorySize, SMEM_FLASH);

    mma_gemm<128, 0><<<dim3(Sc / 128, Hc, Bc), 256>>>(x, kp, vp, nullptr);
    mma_gemm<64, 1><<<dim3(Sc / 128, Hc, Bc), 256>>>(qh, nullptr, nullptr, nullptr);
    flash_mma<<<dim3(Sc / 128, Hc, Bc), 256, SMEM_FLASH>>>();
    mma_gemm<128, 2><<<dim3(Bc * Sc / 128, Ec / 128), 256>>>(lw, nullptr, nullptr, out);
}

// round 7
// speedup vs baseline: 3.4440x; 1.1662x over previous
#include <cuda_runtime.h>
#include <math.h>
#include <stdint.h>

namespace {

constexpr int Bc = 8, Sc = 1024, Ec = 768, Hc = 12, Pc = 64, HPc = 768;

__device__ float g_k[Bc * Hc * Sc * Pc];
__device__ float g_v[Bc * Hc * Sc * Pc];     // tf32-rounded at producer
__device__ float g_qv[Bc * Hc * Sc * Pc];    // tf32-rounded at producer
__device__ float g_attn[Bc * Sc * HPc];

__device__ __forceinline__ float to_tf32(float x) {
    float y;
    asm("cvt.rna.tf32.f32 %0, %1;" : "=f"(y) : "f"(x));
    return y;
}

__device__ __forceinline__ void mma_tf32(float c[4], const uint32_t a[4],
                                         const uint32_t b[2]) {
    asm volatile(
        "mma.sync.aligned.m16n8k8.row.col.f32.tf32.tf32.f32 "
        "{%0,%1,%2,%3}, {%4,%5,%6,%7}, {%8,%9}, {%0,%1,%2,%3};"
        : "+f"(c[0]), "+f"(c[1]), "+f"(c[2]), "+f"(c[3])
        : "r"(a[0]), "r"(a[1]), "r"(a[2]), "r"(a[3]), "r"(b[0]), "r"(b[1]));
}

__device__ __forceinline__ uint32_t smem_u32(const void* p) {
    uint32_t a;
    asm("{ .reg .u64 t; cvta.to.shared.u64 t, %1; cvt.u32.u64 %0, t; }"
        : "=r"(a) : "l"(p));
    return a;
}
__device__ __forceinline__ void cp_async16(uint32_t dst, const void* src) {
    asm volatile("cp.async.cg.shared.global [%0], [%1], 16;"
                 :: "r"(dst), "l"(src) : "memory");
}

// ---------------------------------------------------------------------------
// tf32 mma.sync GEMM, double-buffered smem, k-step 32, 1 barrier per step.
// As[2][128][36] (m-major), Bs[2][32][NT+8] (k-major). RNA cvt in store path.
// MODE 0: proj  MODE 1: qv (NT=64)  MODE 2: lift
// ---------------------------------------------------------------------------
template <int NT, int MODE>
__global__ __launch_bounds__(256, 2)
void mma_gemm(const float* __restrict__ P0, const float* __restrict__ P1,
              const float* __restrict__ P2, float* __restrict__ Out) {
    constexpr int WR = (NT == 128) ? 2 : 4;
    constexpr int WC = (NT == 128) ? 4 : 2;
    constexpr int WM = 128 / WR;
    constexpr int WN = NT / WC;
    constexpr int MT = WM / 16;
    constexpr int NTT = WN / 8;
    constexpr int ASTR = 36;
    constexpr int BSTR = NT + 8;
    constexpr int NB4 = (32 * NT) / (4 * 256);

    extern __shared__ float smg[];
    float (*As)[ASTR] = (float(*)[ASTR])smg;                 // [2*128][36]
    float (*Bs)[BSTR] = (float(*)[BSTR])(smg + 2 * 128 * ASTR);  // [2*32][NT+8]

    const int tid = threadIdx.x;
    const int wid = tid >> 5, lane = tid & 31;
    const int wr = (NT == 128) ? (wid >> 2) : (wid >> 1);
    const int wc = (NT == 128) ? (wid & 3) : (wid & 1);
    const int wm0 = wr * WM, wn0 = wc * WN;
    const int qk = lane & 3, qr = lane >> 2;

    const int row0 = blockIdx.x * 128;
    const int hy = blockIdx.y, bz = blockIdx.z;

    const float* A;
    int lda, K;
    const float* Bp = nullptr;
    int ldb = 0;
    const float* kph = nullptr;
    const float* vph = nullptr;
    int n0g = 0;
    if (MODE == 0) {
        A = P0 + (size_t)bz * Sc * Ec; lda = Ec; K = Ec;
        kph = P1 + (size_t)hy * Ec * Pc;
        vph = P2 + (size_t)hy * Ec * Pc;
    } else if (MODE == 1) {
        A = P0 + (size_t)hy * Sc * Sc; lda = Sc; K = Sc;
        Bp = g_v + (size_t)(bz * Hc + hy) * Sc * Pc; ldb = Pc;
    } else {
        A = g_attn; lda = HPc; K = HPc;
        n0g = blockIdx.y * 128;
        Bp = P0 + n0g; ldb = Ec;
    }

    float c[MT][NTT][4];
#pragma unroll
    for (int mt = 0; mt < MT; mt++)
#pragma unroll
        for (int nt = 0; nt < NTT; nt++)
#pragma unroll
            for (int q = 0; q < 4; q++) c[mt][nt][q] = 0.f;

    float4 pa[4], pb[NB4];

    auto loadA = [&](int k0) {
#pragma unroll
        for (int j = 0; j < 4; j++) {
            int i = j * 256 + tid;
            int m = i >> 3, e4 = (i & 7) * 4;
            pa[j] = *(const float4*)(A + (size_t)(row0 + m) * lda + k0 + e4);
        }
    };
    auto loadB = [&](int k0) {
#pragma unroll
        for (int j = 0; j < NB4; j++) {
            int i = j * 256 + tid;
            int kk = (NT == 128) ? (i >> 5) : (i >> 4);
            int n4 = (NT == 128) ? ((i & 31) * 4) : ((i & 15) * 4);
            if (MODE == 0)
                pb[j] = (n4 < 64)
                    ? *(const float4*)(kph + (size_t)(k0 + kk) * Pc + n4)
                    : *(const float4*)(vph + (size_t)(k0 + kk) * Pc + (n4 - 64));
            else
                pb[j] = *(const float4*)(Bp + (size_t)(k0 + kk) * ldb + n4);
        }
    };
    auto storeAB = [&](int buf) {
#pragma unroll
        for (int j = 0; j < 4; j++) {
            int i = j * 256 + tid;
            int m = i >> 3, e4 = (i & 7) * 4;
            float* d = &As[buf * 128 + m][e4];
            d[0] = to_tf32(pa[j].x); d[1] = to_tf32(pa[j].y);
            d[2] = to_tf32(pa[j].z); d[3] = to_tf32(pa[j].w);
        }
#pragma unroll
        for (int j = 0; j < NB4; j++) {
            int i = j * 256 + tid;
            int kk = (NT == 128) ? (i >> 5) : (i >> 4);
            int n4 = (NT == 128) ? ((i & 31) * 4) : ((i & 15) * 4);
            float* d = &Bs[buf * 32 + kk][n4];
            d[0] = to_tf32(pb[j].x); d[1] = to_tf32(pb[j].y);
            d[2] = to_tf32(pb[j].z); d[3] = to_tf32(pb[j].w);
        }
    };

    loadA(0); loadB(0);
    storeAB(0);
    __syncthreads();

    const int nT = K / 32;
    for (int t = 0; t < nT; t++) {
        if (t + 1 < nT) { loadA((t + 1) * 32); loadB((t + 1) * 32); }
        const int ab = (t & 1) * 128, bb = (t & 1) * 32;
#pragma unroll
        for (int kk8 = 0; kk8 < 32; kk8 += 8) {
            uint32_t a[MT][4], b[NTT][2];
#pragma unroll
            for (int mt = 0; mt < MT; mt++) {
                int m0 = wm0 + mt * 16;
                a[mt][0] = __float_as_uint(As[ab + m0 + qr][kk8 + qk]);
                a[mt][1] = __float_as_uint(As[ab + m0 + qr + 8][kk8 + qk]);
                a[mt][2] = __float_as_uint(As[ab + m0 + qr][kk8 + qk + 4]);
                a[mt][3] = __float_as_uint(As[ab + m0 + qr + 8][kk8 + qk + 4]);
            }
#pragma unroll
            for (int nt = 0; nt < NTT; nt++) {
                int n0 = wn0 + nt * 8;
                b[nt][0] = __float_as_uint(Bs[bb + kk8 + qk][n0 + qr]);
                b[nt][1] = __float_as_uint(Bs[bb + kk8 + qk + 4][n0 + qr]);
            }
#pragma unroll
            for (int mt = 0; mt < MT; mt++)
#pragma unroll
                for (int nt = 0; nt < NTT; nt++)
                    mma_tf32(c[mt][nt], a[mt], b[nt]);
        }
        if (t + 1 < nT) storeAB((t + 1) & 1);
        __syncthreads();
    }

#pragma unroll
    for (int mt = 0; mt < MT; mt++) {
#pragma unroll
        for (int nt = 0; nt < NTT; nt++) {
            int row = row0 + wm0 + mt * 16 + qr;
            int col = wn0 + nt * 8 + 2 * qk;
            float2 lo = make_float2(c[mt][nt][0], c[mt][nt][1]);
            float2 hi = make_float2(c[mt][nt][2], c[mt][nt][3]);
            if (MODE == 0) {
                size_t off = (size_t)(bz * Hc + hy) * Sc * Pc;
                int cc = col & 63;
                if (col < 64) {   // g_k: raw (flash rounds after scaling)
                    *(float2*)(g_k + off + (size_t)row * Pc + cc) = lo;
                    *(float2*)(g_k + off + (size_t)(row + 8) * Pc + cc) = hi;
                } else {          // g_v: pre-round for flash cp.async path
                    lo.x = to_tf32(lo.x); lo.y = to_tf32(lo.y);
                    hi.x = to_tf32(hi.x); hi.y = to_tf32(hi.y);
                    *(float2*)(g_v + off + (size_t)row * Pc + cc) = lo;
                    *(float2*)(g_v + off + (size_t)(row + 8) * Pc + cc) = hi;
                }
            } else if (MODE == 1) {
                float* base = g_qv + (size_t)(bz * Hc + hy) * Sc * Pc;
                lo.x = to_tf32(lo.x); lo.y = to_tf32(lo.y);
                hi.x = to_tf32(hi.x); hi.y = to_tf32(hi.y);
                *(float2*)(base + (size_t)row * Pc + col) = lo;
                *(float2*)(base + (size_t)(row + 8) * Pc + col) = hi;
            } else {
                *(float2*)(Out + (size_t)row * Ec + n0g + col) = lo;
                *(float2*)(Out + (size_t)(row + 8) * Ec + n0g + col) = hi;
            }
        }
    }
}

constexpr int SMG128 = (2 * 128 * 36 + 2 * 32 * 136) * (int)sizeof(float);
constexpr int SMG64  = (2 * 128 * 36 + 2 * 32 * 72) * (int)sizeof(float);

// ---------------------------------------------------------------------------
// Flash attention, mma.sync tf32.  Q = k/sqrt(E) (regs), K = qv, V = v
// (cp.async double-buffered, pre-rounded at producers).  Ps in smem.
// Ks[2][128][68], Vs[2][128][72], Ps[128][132].
// ---------------------------------------------------------------------------
constexpr int KSOFF = 2 * 128 * 68;
constexpr int VSOFF = KSOFF + 2 * 128 * 72;
constexpr int SMEM_FLASH = (VSOFF + 128 * 132) * (int)sizeof(float);

__global__ __launch_bounds__(256, 1)
void flash_mma() {
    extern __shared__ float smf[];
    float (*Ks)[68]  = (float(*)[68])smf;
    float (*Vs)[72]  = (float(*)[72])(smf + KSOFF);
    float (*Ps)[132] = (float(*)[132])(smf + VSOFF);
    const uint32_t ks_base = smem_u32(smf);
    const uint32_t vs_base = smem_u32(smf + KSOFF);

    const int i0 = (gridDim.x - 1 - blockIdx.x) * 128;  // heavy blocks first
    const int h = blockIdx.y, b = blockIdx.z;
    const int tid = threadIdx.x;
    const int wid = tid >> 5, lane = tid & 31;
    const int qk = lane & 3, qr = lane >> 2;
    const int m0 = wid * 16;

    const size_t base = (size_t)(b * Hc + h) * Sc * Pc;
    const float* kb  = g_k  + base;
    const float* qvb = g_qv + base;
    const float* vb  = g_v  + base;
    const float qscale = rsqrtf((float)Ec);

    // Q fragments in registers (one-time gmem gather, scaled + rounded)
    uint32_t qa[8][4];
    {
        const int r0g = i0 + m0 + qr, r1g = r0g + 8;
#pragma unroll
        for (int k8 = 0; k8 < 8; k8++) {
            int c0 = k8 * 8 + qk;
            qa[k8][0] = __float_as_uint(to_tf32(kb[(size_t)r0g * Pc + c0] * qscale));
            qa[k8][1] = __float_as_uint(to_tf32(kb[(size_t)r1g * Pc + c0] * qscale));
            qa[k8][2] = __float_as_uint(to_tf32(kb[(size_t)r0g * Pc + c0 + 4] * qscale));
            qa[k8][3] = __float_as_uint(to_tf32(kb[(size_t)r1g * Pc + c0 + 4] * qscale));
        }
    }

    auto fill = [&](int t) {
        const int buf = t & 1;
        const float* ksrc = qvb + (size_t)t * 128 * Pc;
        const float* vsrc = vb + (size_t)t * 128 * Pc;
#pragma unroll
        for (int j = 0; j < 8; j++) {
            int i = j * 256 + tid;          // 0..2047
            int r = i >> 4, c4 = (i & 15) * 4;
            cp_async16(ks_base + (uint32_t)(((buf * 128 + r) * 68 + c4) * 4),
                       ksrc + (size_t)r * Pc + c4);
            cp_async16(vs_base + (uint32_t)(((buf * 128 + r) * 72 + c4) * 4),
                       vsrc + (size_t)r * Pc + c4);
        }
        asm volatile("cp.async.commit_group;" ::: "memory");
    };

    float mrow[2] = {-INFINITY, -INFINITY};
    float lrow[2] = {0.f, 0.f};
    float o[8][4];
#pragma unroll
    for (int nt = 0; nt < 8; nt++)
#pragma unroll
        for (int q = 0; q < 4; q++) o[nt][q] = 0.f;

    const int tN = i0 / 128 + 1;
    fill(0);

    for (int t = 0; t < tN; t++) {
        if (t + 1 < tN) fill(t + 1);
        if (t + 1 < tN)
            asm volatile("cp.async.wait_group 1;" ::: "memory");
        else
            asm volatile("cp.async.wait_group 0;" ::: "memory");
        __syncthreads();
        const int kbuf = (t & 1) * 128;

        // S = Q @ K^T : 16 n-frags, K=64
        float s[16][4];
#pragma unroll
        for (int nt = 0; nt < 16; nt++)
#pragma unroll
            for (int q = 0; q < 4; q++) s[nt][q] = 0.f;

#pragma unroll
        for (int k8 = 0; k8 < 8; k8++) {
            const int kk8 = k8 * 8;
#pragma unroll
            for (int nt = 0; nt < 16; nt++) {
                uint32_t bf[2];
                bf[0] = __float_as_uint(Ks[kbuf + nt * 8 + qr][kk8 + qk]);
                bf[1] = __float_as_uint(Ks[kbuf + nt * 8 + qr][kk8 + qk + 4]);
                mma_tf32(s[nt], qa[k8], bf);
            }
        }

        if (t == tN - 1) {  // diagonal block: causal mask (local indices)
            int r0 = m0 + qr, r1 = r0 + 8;
#pragma unroll
            for (int nt = 0; nt < 16; nt++) {
                int c0 = nt * 8 + 2 * qk;
                if (c0 > r0)     s[nt][0] = -INFINITY;
                if (c0 + 1 > r0) s[nt][1] = -INFINITY;
                if (c0 > r1)     s[nt][2] = -INFINITY;
                if (c0 + 1 > r1) s[nt][3] = -INFINITY;
            }
        }

        // online softmax (quad shuffles)
        float mx0 = mrow[0], mx1 = mrow[1];
#pragma unroll
        for (int nt = 0; nt < 16; nt++) {
            mx0 = fmaxf(mx0, fmaxf(s[nt][0], s[nt][1]));
            mx1 = fmaxf(mx1, fmaxf(s[nt][2], s[nt][3]));
        }
#pragma unroll
        for (int off = 1; off <= 2; off <<= 1) {
            mx0 = fmaxf(mx0, __shfl_xor_sync(0xffffffffu, mx0, off));
            mx1 = fmaxf(mx1, __shfl_xor_sync(0xffffffffu, mx1, off));
        }
        float alpha0 = __expf(mrow[0] - mx0);
        float alpha1 = __expf(mrow[1] - mx1);
        mrow[0] = mx0; mrow[1] = mx1;
        float sum0 = 0.f, sum1 = 0.f;
#pragma unroll
        for (int nt = 0; nt < 16; nt++) {
            int c0 = nt * 8 + 2 * qk;
            float p0 = to_tf32(__expf(s[nt][0] - mx0));
            float p1 = to_tf32(__expf(s[nt][1] - mx0));
            float p2 = to_tf32(__expf(s[nt][2] - mx1));
            float p3 = to_tf32(__expf(s[nt][3] - mx1));
            sum0 += p0 + p1;
            sum1 += p2 + p3;
            *(float2*)&Ps[m0 + qr][c0]     = make_float2(p0, p1);
            *(float2*)&Ps[m0 + qr + 8][c0] = make_float2(p2, p3);
        }
#pragma unroll
        for (int off = 1; off <= 2; off <<= 1) {
            sum0 += __shfl_xor_sync(0xffffffffu, sum0, off);
            sum1 += __shfl_xor_sync(0xffffffffu, sum1, off);
        }
        lrow[0] = lrow[0] * alpha0 + sum0;
        lrow[1] = lrow[1] * alpha1 + sum1;
#pragma unroll
        for (int nt = 0; nt < 8; nt++) {
            o[nt][0] *= alpha0; o[nt][1] *= alpha0;
            o[nt][2] *= alpha1; o[nt][3] *= alpha1;
        }
        __syncwarp();  // Ps rows are warp-private

        // O += P @ V : K=128, 8 n-frags
#pragma unroll
        for (int kk8 = 0; kk8 < 128; kk8 += 8) {
            uint32_t a[4];
            a[0] = __float_as_uint(Ps[m0 + qr][kk8 + qk]);
            a[1] = __float_as_uint(Ps[m0 + qr + 8][kk8 + qk]);
            a[2] = __float_as_uint(Ps[m0 + qr][kk8 + qk + 4]);
            a[3] = __float_as_uint(Ps[m0 + qr + 8][kk8 + qk + 4]);
#pragma unroll
            for (int nt = 0; nt < 8; nt++) {
                uint32_t bf[2];
                bf[0] = __float_as_uint(Vs[kbuf + kk8 + qk][nt * 8 + qr]);
                bf[1] = __float_as_uint(Vs[kbuf + kk8 + qk + 4][nt * 8 + qr]);
                mma_tf32(o[nt], a, bf);
            }
        }
        __syncthreads();  // all warps done with buf before it is refilled
    }

    float inv0 = 1.f / lrow[0], inv1 = 1.f / lrow[1];
    int r0 = i0 + m0 + qr, r1 = r0 + 8;
    float* d0 = g_attn + ((size_t)b * Sc + r0) * HPc + h * Pc;
    float* d1 = g_attn + ((size_t)b * Sc + r1) * HPc + h * Pc;
#pragma unroll
    for (int nt = 0; nt < 8; nt++) {
        int cc = nt * 8 + 2 * qk;
        *(float2*)(d0 + cc) = make_float2(o[nt][0] * inv0, o[nt][1] * inv0);
        *(float2*)(d1 + cc) = make_float2(o[nt][2] * inv1, o[nt][3] * inv1);
    }
}

}  // namespace

extern "C" void kernel_launch(void* const* d_in, const int* in_sizes, int n_in,
                              void* d_out, int out_size) {
    (void)in_sizes; (void)n_in; (void)out_size;
    const float* x  = (const float*)d_in[0];   // (B,1,S,E)
    const float* kp = (const float*)d_in[1];   // (H,E,P)
    const float* vp = (const float*)d_in[2];   // (H,E,P)
    const float* qh = (const float*)d_in[3];   // (H,S,S)
    const float* lw = (const float*)d_in[4];   // (1,HP,E)
    float* out = (float*)d_out;                // (B,S,E)

    cudaFuncSetAttribute(mma_gemm<128, 0>,
                         cudaFuncAttributeMaxDynamicSharedMemorySize, SMG128);
    cudaFuncSetAttribute(mma_gemm<64, 1>,
                         cudaFuncAttributeMaxDynamicSharedMemorySize, SMG64);
    cudaFuncSetAttribute(mma_gemm<128, 2>,
                         cudaFuncAttributeMaxDynamicSharedMemorySize, SMG128);
    cudaFuncSetAttribute(flash_mma,
                         cudaFuncAttributeMaxDynamicSharedMemorySize, SMEM_FLASH);

    mma_gemm<128, 0><<<dim3(Sc / 128, Hc, Bc), 256, SMG128>>>(x, kp, vp, nullptr);
    mma_gemm<64, 1><<<dim3(Sc / 128, Hc, Bc), 256, SMG64>>>(qh, nullptr, nullptr, nullptr);
    flash_mma<<<dim3(Sc / 128, Hc, Bc), 256, SMEM_FLASH>>>();
    mma_gemm<128, 2><<<dim3(Bc * Sc / 128, Ec / 128), 256, SMG128>>>(lw, nullptr, nullptr, out);
}

// round 8
// speedup vs baseline: 3.4980x; 1.0157x over previous
#include <cuda_runtime.h>
#include <math.h>
#include <stdint.h>

namespace {

constexpr int Bc = 8, Sc = 1024, Ec = 768, Hc = 12, Pc = 64, HPc = 768;

__device__ float g_k[Bc * Hc * Sc * Pc];
__device__ float g_v[Bc * Hc * Sc * Pc];     // tf32-rounded at producer
__device__ float g_qv[Bc * Hc * Sc * Pc];    // tf32-rounded at producer
__device__ float g_attn[Bc * Sc * HPc];

__device__ __forceinline__ float to_tf32(float x) {
    float y;
    asm("cvt.rna.tf32.f32 %0, %1;" : "=f"(y) : "f"(x));
    return y;
}

__device__ __forceinline__ void mma_tf32(float c[4], const uint32_t a[4],
                                         const uint32_t b[2]) {
    asm volatile(
        "mma.sync.aligned.m16n8k8.row.col.f32.tf32.tf32.f32 "
        "{%0,%1,%2,%3}, {%4,%5,%6,%7}, {%8,%9}, {%0,%1,%2,%3};"
        : "+f"(c[0]), "+f"(c[1]), "+f"(c[2]), "+f"(c[3])
        : "r"(a[0]), "r"(a[1]), "r"(a[2]), "r"(a[3]), "r"(b[0]), "r"(b[1]));
}

__device__ __forceinline__ uint32_t smem_u32(const void* p) {
    uint32_t a;
    asm("{ .reg .u64 t; cvta.to.shared.u64 t, %1; cvt.u32.u64 %0, t; }"
        : "=r"(a) : "l"(p));
    return a;
}
__device__ __forceinline__ void cp_async16(uint32_t dst, const void* src) {
    asm volatile("cp.async.cg.shared.global [%0], [%1], 16;"
                 :: "r"(dst), "l"(src) : "memory");
}

// ---------------------------------------------------------------------------
// tf32 mma.sync GEMM, double-buffered, k-step 32.
// A staged in FRAGMENT ORDER: Ax[chunk = (buf*8+mtile)*4+k8][lane] = float4
// (a0,a1,a2,a3) for that lane -> mma A-frag = ONE LDS.128 at base+laneid*16.
// Chunk stride 33 float4s (bank-spread for the writer scatter).
// B plain [k][n] stride NT+8 (conflict-free 2x LDS.32 per n-frag).
// MODE 0: proj  MODE 1: qv (NT=64)  MODE 2: lift
// ---------------------------------------------------------------------------
constexpr int ACH = 33;                       // float4 per chunk (32 + 1 pad)
constexpr int AFLOATS = 2 * 8 * 4 * ACH * 4;  // floats in A region

template <int NT, int MODE>
__global__ __launch_bounds__(256, 2)
void mma_gemm(const float* __restrict__ P0, const float* __restrict__ P1,
              const float* __restrict__ P2, float* __restrict__ Out) {
    constexpr int WR = (NT == 128) ? 2 : 4;
    constexpr int WC = (NT == 128) ? 4 : 2;
    constexpr int WM = 128 / WR;
    constexpr int WN = NT / WC;
    constexpr int MT = WM / 16;
    constexpr int NTT = WN / 8;
    constexpr int BSTR = NT + 8;
    constexpr int NB4 = (32 * NT) / (4 * 256);

    extern __shared__ float smg[];
    float4* Ax = (float4*)smg;                       // fragment-order A
    float (*Bs)[BSTR] = (float(*)[BSTR])(smg + AFLOATS);

    const int tid = threadIdx.x;
    const int wid = tid >> 5, lane = tid & 31;
    const int wr = (NT == 128) ? (wid >> 2) : (wid >> 1);
    const int wc = (NT == 128) ? (wid & 3) : (wid & 1);
    const int wm0 = wr * WM, wn0 = wc * WN;
    const int qk = lane & 3, qr = lane >> 2;
    const int mtile0 = wm0 >> 4;

    const int row0 = blockIdx.x * 128;
    const int hy = blockIdx.y, bz = blockIdx.z;

    const float* A;
    int lda, K;
    const float* Bp = nullptr;
    int ldb = 0;
    const float* kph = nullptr;
    const float* vph = nullptr;
    int n0g = 0;
    if (MODE == 0) {
        A = P0 + (size_t)bz * Sc * Ec; lda = Ec; K = Ec;
        kph = P1 + (size_t)hy * Ec * Pc;
        vph = P2 + (size_t)hy * Ec * Pc;
    } else if (MODE == 1) {
        A = P0 + (size_t)hy * Sc * Sc; lda = Sc; K = Sc;
        Bp = g_v + (size_t)(bz * Hc + hy) * Sc * Pc; ldb = Pc;
    } else {
        A = g_attn; lda = HPc; K = HPc;
        n0g = blockIdx.y * 128;
        Bp = P0 + n0g; ldb = Ec;
    }

    float c[MT][NTT][4];
#pragma unroll
    for (int mt = 0; mt < MT; mt++)
#pragma unroll
        for (int nt = 0; nt < NTT; nt++)
#pragma unroll
            for (int q = 0; q < 4; q++) c[mt][nt][q] = 0.f;

    float4 pa[4], pb[NB4];

    auto loadA = [&](int k0) {
#pragma unroll
        for (int j = 0; j < 4; j++) {
            int i = j * 256 + tid;
            int m = i >> 3, e4 = (i & 7) * 4;
            pa[j] = *(const float4*)(A + (size_t)(row0 + m) * lda + k0 + e4);
        }
    };
    auto loadB = [&](int k0) {
#pragma unroll
        for (int j = 0; j < NB4; j++) {
            int i = j * 256 + tid;
            int kk = (NT == 128) ? (i >> 5) : (i >> 4);
            int n4 = (NT == 128) ? ((i & 31) * 4) : ((i & 15) * 4);
            if (MODE == 0)
                pb[j] = (n4 < 64)
                    ? *(const float4*)(kph + (size_t)(k0 + kk) * Pc + n4)
                    : *(const float4*)(vph + (size_t)(k0 + kk) * Pc + (n4 - 64));
            else
                pb[j] = *(const float4*)(Bp + (size_t)(k0 + kk) * ldb + n4);
        }
    };
    auto storeAB = [&](int buf) {
#pragma unroll
        for (int j = 0; j < 4; j++) {
            int i = j * 256 + tid;
            int m = i >> 3, e4 = (i & 7) * 4;
            // fragment-order scatter
            int mtile = m >> 4, k8 = e4 >> 3;
            int comp = ((m >> 3) & 1) | (((e4 >> 2) & 1) << 1);
            int lane0 = (m & 7) * 4;
            float* dst = smg + (((buf * 8 + mtile) * 4 + k8) * ACH + lane0) * 4 + comp;
            dst[0]  = to_tf32(pa[j].x);
            dst[4]  = to_tf32(pa[j].y);
            dst[8]  = to_tf32(pa[j].z);
            dst[12] = to_tf32(pa[j].w);
        }
#pragma unroll
        for (int j = 0; j < NB4; j++) {
            int i = j * 256 + tid;
            int kk = (NT == 128) ? (i >> 5) : (i >> 4);
            int n4 = (NT == 128) ? ((i & 31) * 4) : ((i & 15) * 4);
            float* d = &Bs[buf * 32 + kk][n4];
            d[0] = to_tf32(pb[j].x); d[1] = to_tf32(pb[j].y);
            d[2] = to_tf32(pb[j].z); d[3] = to_tf32(pb[j].w);
        }
    };

    loadA(0); loadB(0);
    storeAB(0);
    __syncthreads();

    const int nT = K / 32;
    for (int t = 0; t < nT; t++) {
        if (t + 1 < nT) { loadA((t + 1) * 32); loadB((t + 1) * 32); }
        const int ab8 = (t & 1) * 8, bb = (t & 1) * 32;
#pragma unroll
        for (int k8 = 0; k8 < 4; k8++) {
            const int kk8 = k8 * 8;
            uint32_t a[MT][4], b[NTT][2];
#pragma unroll
            for (int mt = 0; mt < MT; mt++) {
                float4 av = Ax[((ab8 + mtile0 + mt) * 4 + k8) * ACH + lane];
                a[mt][0] = __float_as_uint(av.x);
                a[mt][1] = __float_as_uint(av.y);
                a[mt][2] = __float_as_uint(av.z);
                a[mt][3] = __float_as_uint(av.w);
            }
#pragma unroll
            for (int nt = 0; nt < NTT; nt++) {
                int n0 = wn0 + nt * 8;
                b[nt][0] = __float_as_uint(Bs[bb + kk8 + qk][n0 + qr]);
                b[nt][1] = __float_as_uint(Bs[bb + kk8 + qk + 4][n0 + qr]);
            }
#pragma unroll
            for (int mt = 0; mt < MT; mt++)
#pragma unroll
                for (int nt = 0; nt < NTT; nt++)
                    mma_tf32(c[mt][nt], a[mt], b[nt]);
        }
        if (t + 1 < nT) storeAB((t + 1) & 1);
        __syncthreads();
    }

#pragma unroll
    for (int mt = 0; mt < MT; mt++) {
#pragma unroll
        for (int nt = 0; nt < NTT; nt++) {
            int row = row0 + wm0 + mt * 16 + qr;
            int col = wn0 + nt * 8 + 2 * qk;
            float2 lo = make_float2(c[mt][nt][0], c[mt][nt][1]);
            float2 hi = make_float2(c[mt][nt][2], c[mt][nt][3]);
            if (MODE == 0) {
                size_t off = (size_t)(bz * Hc + hy) * Sc * Pc;
                int cc = col & 63;
                if (col < 64) {   // g_k: raw (flash rounds after scaling)
                    *(float2*)(g_k + off + (size_t)row * Pc + cc) = lo;
                    *(float2*)(g_k + off + (size_t)(row + 8) * Pc + cc) = hi;
                } else {          // g_v: pre-round for flash cp.async path
                    lo.x = to_tf32(lo.x); lo.y = to_tf32(lo.y);
                    hi.x = to_tf32(hi.x); hi.y = to_tf32(hi.y);
                    *(float2*)(g_v + off + (size_t)row * Pc + cc) = lo;
                    *(float2*)(g_v + off + (size_t)(row + 8) * Pc + cc) = hi;
                }
            } else if (MODE == 1) {
                float* base = g_qv + (size_t)(bz * Hc + hy) * Sc * Pc;
                lo.x = to_tf32(lo.x); lo.y = to_tf32(lo.y);
                hi.x = to_tf32(hi.x); hi.y = to_tf32(hi.y);
                *(float2*)(base + (size_t)row * Pc + col) = lo;
                *(float2*)(base + (size_t)(row + 8) * Pc + col) = hi;
            } else {
                *(float2*)(Out + (size_t)row * Ec + n0g + col) = lo;
                *(float2*)(Out + (size_t)(row + 8) * Ec + n0g + col) = hi;
            }
        }
    }
}

constexpr int SMG128 = (AFLOATS + 2 * 32 * 136) * (int)sizeof(float);
constexpr int SMG64  = (AFLOATS + 2 * 32 * 72) * (int)sizeof(float);

// ---------------------------------------------------------------------------
// Flash attention, mma.sync tf32.  Q = k/sqrt(E) (regs), K = qv, V = v
// (cp.async double-buffered, pre-rounded at producers).  Ps in smem.
// Ks[2][128][68], Vs[2][128][72], Ps[128][132].
// ---------------------------------------------------------------------------
constexpr int KSOFF = 2 * 128 * 68;
constexpr int VSOFF = KSOFF + 2 * 128 * 72;
constexpr int SMEM_FLASH = (VSOFF + 128 * 132) * (int)sizeof(float);

__global__ __launch_bounds__(256, 1)
void flash_mma() {
    extern __shared__ float smf[];
    float (*Ks)[68]  = (float(*)[68])smf;
    float (*Vs)[72]  = (float(*)[72])(smf + KSOFF);
    float (*Ps)[132] = (float(*)[132])(smf + VSOFF);
    const uint32_t ks_base = smem_u32(smf);
    const uint32_t vs_base = smem_u32(smf + KSOFF);

    const int i0 = (gridDim.x - 1 - blockIdx.x) * 128;  // heavy blocks first
    const int h = blockIdx.y, b = blockIdx.z;
    const int tid = threadIdx.x;
    const int wid = tid >> 5, lane = tid & 31;
    const int qk = lane & 3, qr = lane >> 2;
    const int m0 = wid * 16;

    const size_t base = (size_t)(b * Hc + h) * Sc * Pc;
    const float* kb  = g_k  + base;
    const float* qvb = g_qv + base;
    const float* vb  = g_v  + base;
    const float qscale = rsqrtf((float)Ec);

    // Q fragments in registers (one-time gmem gather, scaled + rounded)
    uint32_t qa[8][4];
    {
        const int r0g = i0 + m0 + qr, r1g = r0g + 8;
#pragma unroll
        for (int k8 = 0; k8 < 8; k8++) {
            int c0 = k8 * 8 + qk;
            qa[k8][0] = __float_as_uint(to_tf32(kb[(size_t)r0g * Pc + c0] * qscale));
            qa[k8][1] = __float_as_uint(to_tf32(kb[(size_t)r1g * Pc + c0] * qscale));
            qa[k8][2] = __float_as_uint(to_tf32(kb[(size_t)r0g * Pc + c0 + 4] * qscale));
            qa[k8][3] = __float_as_uint(to_tf32(kb[(size_t)r1g * Pc + c0 + 4] * qscale));
        }
    }

    auto fill = [&](int t) {
        const int buf = t & 1;
        const float* ksrc = qvb + (size_t)t * 128 * Pc;
        const float* vsrc = vb + (size_t)t * 128 * Pc;
#pragma unroll
        for (int j = 0; j < 8; j++) {
            int i = j * 256 + tid;          // 0..2047
            int r = i >> 4, c4 = (i & 15) * 4;
            cp_async16(ks_base + (uint32_t)(((buf * 128 + r) * 68 + c4) * 4),
                       ksrc + (size_t)r * Pc + c4);
            cp_async16(vs_base + (uint32_t)(((buf * 128 + r) * 72 + c4) * 4),
                       vsrc + (size_t)r * Pc + c4);
        }
        asm volatile("cp.async.commit_group;" ::: "memory");
    };

    float mrow[2] = {-INFINITY, -INFINITY};
    float lrow[2] = {0.f, 0.f};
    float o[8][4];
#pragma unroll
    for (int nt = 0; nt < 8; nt++)
#pragma unroll
        for (int q = 0; q < 4; q++) o[nt][q] = 0.f;

    const int tN = i0 / 128 + 1;
    fill(0);

    for (int t = 0; t < tN; t++) {
        if (t + 1 < tN) fill(t + 1);
        if (t + 1 < tN)
            asm volatile("cp.async.wait_group 1;" ::: "memory");
        else
            asm volatile("cp.async.wait_group 0;" ::: "memory");
        __syncthreads();
        const int kbuf = (t & 1) * 128;

        // S = Q @ K^T : 16 n-frags, K=64
        float s[16][4];
#pragma unroll
        for (int nt = 0; nt < 16; nt++)
#pragma unroll
            for (int q = 0; q < 4; q++) s[nt][q] = 0.f;

#pragma unroll
        for (int k8 = 0; k8 < 8; k8++) {
            const int kk8 = k8 * 8;
#pragma unroll
            for (int nt = 0; nt < 16; nt++) {
                uint32_t bf[2];
                bf[0] = __float_as_uint(Ks[kbuf + nt * 8 + qr][kk8 + qk]);
                bf[1] = __float_as_uint(Ks[kbuf + nt * 8 + qr][kk8 + qk + 4]);
                mma_tf32(s[nt], qa[k8], bf);
            }
        }

        if (t == tN - 1) {  // diagonal block: causal mask (local indices)
            int r0 = m0 + qr, r1 = r0 + 8;
#pragma unroll
            for (int nt = 0; nt < 16; nt++) {
                int c0 = nt * 8 + 2 * qk;
                if (c0 > r0)     s[nt][0] = -INFINITY;
                if (c0 + 1 > r0) s[nt][1] = -INFINITY;
                if (c0 > r1)     s[nt][2] = -INFINITY;
                if (c0 + 1 > r1) s[nt][3] = -INFINITY;
            }
        }

        // online softmax (quad shuffles)
        float mx0 = mrow[0], mx1 = mrow[1];
#pragma unroll
        for (int nt = 0; nt < 16; nt++) {
            mx0 = fmaxf(mx0, fmaxf(s[nt][0], s[nt][1]));
            mx1 = fmaxf(mx1, fmaxf(s[nt][2], s[nt][3]));
        }
#pragma unroll
        for (int off = 1; off <= 2; off <<= 1) {
            mx0 = fmaxf(mx0, __shfl_xor_sync(0xffffffffu, mx0, off));
            mx1 = fmaxf(mx1, __shfl_xor_sync(0xffffffffu, mx1, off));
        }
        float alpha0 = __expf(mrow[0] - mx0);
        float alpha1 = __expf(mrow[1] - mx1);
        mrow[0] = mx0; mrow[1] = mx1;
        float sum0 = 0.f, sum1 = 0.f;
#pragma unroll
        for (int nt = 0; nt < 16; nt++) {
            int c0 = nt * 8 + 2 * qk;
            float p0 = to_tf32(__expf(s[nt][0] - mx0));
            float p1 = to_tf32(__expf(s[nt][1] - mx0));
            float p2 = to_tf32(__expf(s[nt][2] - mx1));
            float p3 = to_tf32(__expf(s[nt][3] - mx1));
            sum0 += p0 + p1;
            sum1 += p2 + p3;
            *(float2*)&Ps[m0 + qr][c0]     = make_float2(p0, p1);
            *(float2*)&Ps[m0 + qr + 8][c0] = make_float2(p2, p3);
        }
#pragma unroll
        for (int off = 1; off <= 2; off <<= 1) {
            sum0 += __shfl_xor_sync(0xffffffffu, sum0, off);
            sum1 += __shfl_xor_sync(0xffffffffu, sum1, off);
        }
        lrow[0] = lrow[0] * alpha0 + sum0;
        lrow[1] = lrow[1] * alpha1 + sum1;
#pragma unroll
        for (int nt = 0; nt < 8; nt++) {
            o[nt][0] *= alpha0; o[nt][1] *= alpha0;
            o[nt][2] *= alpha1; o[nt][3] *= alpha1;
        }
        __syncwarp();  // Ps rows are warp-private

        // O += P @ V : K=128, 8 n-frags
#pragma unroll
        for (int kk8 = 0; kk8 < 128; kk8 += 8) {
            uint32_t a[4];
            a[0] = __float_as_uint(Ps[m0 + qr][kk8 + qk]);
            a[1] = __float_as_uint(Ps[m0 + qr + 8][kk8 + qk]);
            a[2] = __float_as_uint(Ps[m0 + qr][kk8 + qk + 4]);
            a[3] = __float_as_uint(Ps[m0 + qr + 8][kk8 + qk + 4]);
#pragma unroll
            for (int nt = 0; nt < 8; nt++) {
                uint32_t bf[2];
                bf[0] = __float_as_uint(Vs[kbuf + kk8 + qk][nt * 8 + qr]);
                bf[1] = __float_as_uint(Vs[kbuf + kk8 + qk + 4][nt * 8 + qr]);
                mma_tf32(o[nt], a, bf);
            }
        }
        __syncthreads();  // all warps done with buf before it is refilled
    }

    float inv0 = 1.f / lrow[0], inv1 = 1.f / lrow[1];
    int r0 = i0 + m0 + qr, r1 = r0 + 8;
    float* d0 = g_attn + ((size_t)b * Sc + r0) * HPc + h * Pc;
    float* d1 = g_attn + ((size_t)b * Sc + r1) * HPc + h * Pc;
#pragma unroll
    for (int nt = 0; nt < 8; nt++) {
        int cc = nt * 8 + 2 * qk;
        *(float2*)(d0 + cc) = make_float2(o[nt][0] * inv0, o[nt][1] * inv0);
        *(float2*)(d1 + cc) = make_float2(o[nt][2] * inv1, o[nt][3] * inv1);
    }
}

}  // namespace

extern "C" void kernel_launch(void* const* d_in, const int* in_sizes, int n_in,
                              void* d_out, int out_size) {
    (void)in_sizes; (void)n_in; (void)out_size;
    const float* x  = (const float*)d_in[0];   // (B,1,S,E)
    const float* kp = (const float*)d_in[1];   // (H,E,P)
    const float* vp = (const float*)d_in[2];   // (H,E,P)
    const float* qh = (const float*)d_in[3];   // (H,S,S)
    const float* lw = (const float*)d_in[4];   // (1,HP,E)
    float* out = (float*)d_out;                // (B,S,E)

    cudaFuncSetAttribute(mma_gemm<128, 0>,
                         cudaFuncAttributeMaxDynamicSharedMemorySize, SMG128);
    cudaFuncSetAttribute(mma_gemm<64, 1>,
                         cudaFuncAttributeMaxDynamicSharedMemorySize, SMG64);
    cudaFuncSetAttribute(mma_gemm<128, 2>,
                         cudaFuncAttributeMaxDynamicSharedMemorySize, SMG128);
    cudaFuncSetAttribute(flash_mma,
                         cudaFuncAttributeMaxDynamicSharedMemorySize, SMEM_FLASH);

    mma_gemm<128, 0><<<dim3(Sc / 128, Hc, Bc), 256, SMG128>>>(x, kp, vp, nullptr);
    mma_gemm<64, 1><<<dim3(Sc / 128, Hc, Bc), 256, SMG64>>>(qh, nullptr, nullptr, nullptr);
    flash_mma<<<dim3(Sc / 128, Hc, Bc), 256, SMEM_FLASH>>>();
    mma_gemm<128, 2><<<dim3(Bc * Sc / 128, Ec / 128), 256, SMG128>>>(lw, nullptr, nullptr, out);
}

// round 10
// speedup vs baseline: 3.7571x; 1.0741x over previous
#include <cuda_runtime.h>
#include <math.h>
#include <stdint.h>

namespace {

constexpr int Bc = 8, Sc = 1024, Ec = 768, Hc = 12, Pc = 64, HPc = 768;

__device__ float g_k[Bc * Hc * Sc * Pc];
__device__ float g_v[Bc * Hc * Sc * Pc];     // tf32-rounded at producer
__device__ float g_qv[Bc * Hc * Sc * Pc];    // tf32-rounded at producer
__device__ float g_attn[Bc * Sc * HPc];      // tf32-rounded at producer (flash)
__device__ float g_wkv[Hc * Ec * 128];       // rounded kp||vp, [h][e][128]
__device__ float g_lw[HPc * Ec];             // rounded lifting

__device__ __forceinline__ float to_tf32(float x) {
    float y;
    asm("cvt.rna.tf32.f32 %0, %1;" : "=f"(y) : "f"(x));
    return y;
}

__device__ __forceinline__ void mma_tf32(float c[4], const uint32_t a[4],
                                         const uint32_t b[2]) {
    asm volatile(
        "mma.sync.aligned.m16n8k8.row.col.f32.tf32.tf32.f32 "
        "{%0,%1,%2,%3}, {%4,%5,%6,%7}, {%8,%9}, {%0,%1,%2,%3};"
        : "+f"(c[0]), "+f"(c[1]), "+f"(c[2]), "+f"(c[3])
        : "r"(a[0]), "r"(a[1]), "r"(a[2]), "r"(a[3]), "r"(b[0]), "r"(b[1]));
}

__device__ __forceinline__ uint32_t smem_u32(const void* p) {
    uint32_t a;
    asm("{ .reg .u64 t; cvta.to.shared.u64 t, %1; cvt.u32.u64 %0, t; }"
        : "=r"(a) : "l"(p));
    return a;
}
__device__ __forceinline__ void cp_async16(uint32_t dst, const void* src) {
    asm volatile("cp.async.cg.shared.global [%0], [%1], 16;"
                 :: "r"(dst), "l"(src) : "memory");
}
#define CP_COMMIT() asm volatile("cp.async.commit_group;" ::: "memory")
#define CP_WAIT0()  asm volatile("cp.async.wait_group 0;" ::: "memory")

// ---------------------------------------------------------------------------
// Prologue: RNA-round the weights into scratch (enables cp.async B paths).
// region 1: g_wkv[h][e][n] = rna(n<64 ? kp[h][e][n] : vp[h][e][n-64])
// region 2: g_lw = rna(lifting)
// ---------------------------------------------------------------------------
constexpr int RW_N1 = Hc * Ec * 128 / 4;   // float4 count
constexpr int RW_N2 = HPc * Ec / 4;

__global__ __launch_bounds__(256)
void round_weights(const float* __restrict__ kp, const float* __restrict__ vp,
                   const float* __restrict__ lw) {
    int idx = blockIdx.x * 256 + threadIdx.x;
    if (idx < RW_N1) {
        int n4 = (idx & 31) * 4;
        int e = (idx >> 5) % Ec;
        int h = idx / (32 * Ec);
        float4 v = (n4 < 64)
            ? *(const float4*)(kp + ((size_t)h * Ec + e) * Pc + n4)
            : *(const float4*)(vp + ((size_t)h * Ec + e) * Pc + (n4 - 64));
        v.x = to_tf32(v.x); v.y = to_tf32(v.y);
        v.z = to_tf32(v.z); v.w = to_tf32(v.w);
        ((float4*)g_wkv)[idx] = v;
    } else if (idx < RW_N1 + RW_N2) {
        int f = idx - RW_N1;
        float4 v = ((const float4*)lw)[f];
        v.x = to_tf32(v.x); v.y = to_tf32(v.y);
        v.z = to_tf32(v.z); v.w = to_tf32(v.w);
        ((float4*)g_lw)[f] = v;
    }
}

// ---------------------------------------------------------------------------
// tf32 mma.sync GEMM, double-buffered, k-step 32.
// B always via cp.async (operands pre-rounded in gmem).
// A: MODE 0/1 raw gmem -> reg stage + RNA cvt -> fragment-order smem
//    (one LDS.128 per A-frag).  MODE 2: pre-rounded -> cp.async, plain
//    [m][36] rows (4x conflict-free LDS.32 per frag).
// MODE 0: proj  MODE 1: qv (NT=64)  MODE 2: lift
// ---------------------------------------------------------------------------
constexpr int ACH = 33;                    // float4 per frag-order chunk
constexpr int AFL = 2 * 128 * 36;          // floats in A region (max of layouts)

template <int NT, int MODE>
__global__ __launch_bounds__(256, 2)
void mma_gemm(const float* __restrict__ P0, float* __restrict__ Out) {
    constexpr bool CPA = (MODE == 2);      // A via cp.async
    constexpr int WR = (NT == 128) ? 2 : 4;
    constexpr int WC = (NT == 128) ? 4 : 2;
    constexpr int WM = 128 / WR;
    constexpr int WN = NT / WC;
    constexpr int MT = WM / 16;
    constexpr int NTT = WN / 8;
    constexpr int BSTR = NT + 8;
    constexpr int NB4 = (32 * NT) / (4 * 256);

    extern __shared__ float smg[];
    float4* Ax = (float4*)smg;                         // frag-order (MODE 0/1)
    float (*Asp)[36] = (float(*)[36])smg;              // plain (MODE 2)
    float (*Bs)[BSTR] = (float(*)[BSTR])(smg + AFL);
    const uint32_t as_base = smem_u32(smg);
    const uint32_t bs_base = smem_u32(smg + AFL);

    const int tid = threadIdx.x;
    const int wid = tid >> 5, lane = tid & 31;
    const int wr = (NT == 128) ? (wid >> 2) : (wid >> 1);
    const int wc = (NT == 128) ? (wid & 3) : (wid & 1);
    const int wm0 = wr * WM, wn0 = wc * WN;
    const int qk = lane & 3, qr = lane >> 2;
    const int mtile0 = wm0 >> 4;

    const int row0 = blockIdx.x * 128;
    const int hy = blockIdx.y, bz = blockIdx.z;

    const float* A;
    int lda, K;
    const float* Bg = nullptr;   // cp.async B source base
    int ldb = 0;
    int n0g = 0;
    if (MODE == 0) {
        A = P0 + (size_t)bz * Sc * Ec; lda = Ec; K = Ec;
        Bg = g_wkv + (size_t)hy * Ec * 128; ldb = 128;
    } else if (MODE == 1) {
        A = P0 + (size_t)hy * Sc * Sc; lda = Sc; K = Sc;
        Bg = g_v + (size_t)(bz * Hc + hy) * Sc * Pc; ldb = Pc;
    } else {
        A = g_attn; lda = HPc; K = HPc;
        n0g = blockIdx.y * 128;
        Bg = g_lw + n0g; ldb = Ec;
    }

    float c[MT][NTT][4];
#pragma unroll
    for (int mt = 0; mt < MT; mt++)
#pragma unroll
        for (int nt = 0; nt < NTT; nt++)
#pragma unroll
            for (int q = 0; q < 4; q++) c[mt][nt][q] = 0.f;

    float4 pa[4];

    auto fillB = [&](int t) {
        const int k0 = t * 32, buf = t & 1;
#pragma unroll
        for (int j = 0; j < NB4; j++) {
            int i = j * 256 + tid;
            int kk = (NT == 128) ? (i >> 5) : (i >> 4);
            int n4 = (NT == 128) ? ((i & 31) * 4) : ((i & 15) * 4);
            cp_async16(bs_base + (uint32_t)(((buf * 32 + kk) * BSTR + n4) * 4),
                       Bg + (size_t)(k0 + kk) * ldb + n4);
        }
    };
    auto fillA_cp = [&](int t) {   // MODE 2
        const int k0 = t * 32, buf = t & 1;
#pragma unroll
        for (int j = 0; j < 4; j++) {
            int i = j * 256 + tid;
            int m = i >> 3, e4 = (i & 7) * 4;
            cp_async16(as_base + (uint32_t)(((buf * 128 + m) * 36 + e4) * 4),
                       A + (size_t)(row0 + m) * lda + k0 + e4);
        }
    };
    auto loadA = [&](int k0) {     // MODE 0/1
#pragma unroll
        for (int j = 0; j < 4; j++) {
            int i = j * 256 + tid;
            int m = i >> 3, e4 = (i & 7) * 4;
            pa[j] = *(const float4*)(A + (size_t)(row0 + m) * lda + k0 + e4);
        }
    };
    auto storeA = [&](int buf) {   // MODE 0/1, fragment-order + RNA
#pragma unroll
        for (int j = 0; j < 4; j++) {
            int i = j * 256 + tid;
            int m = i >> 3, e4 = (i & 7) * 4;
            int mtile = m >> 4, k8 = e4 >> 3;
            int comp = ((m >> 3) & 1) | (((e4 >> 2) & 1) << 1);
            int lane0 = (m & 7) * 4;
            float* dst = smg + (((buf * 8 + mtile) * 4 + k8) * ACH + lane0) * 4 + comp;
            dst[0]  = to_tf32(pa[j].x);
            dst[4]  = to_tf32(pa[j].y);
            dst[8]  = to_tf32(pa[j].z);
            dst[12] = to_tf32(pa[j].w);
        }
    };

    // prologue: stage 0
    fillB(0);
    if constexpr (CPA) fillA_cp(0);
    CP_COMMIT();
    if constexpr (!CPA) { loadA(0); storeA(0); }
    CP_WAIT0();
    __syncthreads();

    const int nT = K / 32;
    for (int t = 0; t < nT; t++) {
        if (t + 1 < nT) {
            fillB(t + 1);
            if constexpr (CPA) fillA_cp(t + 1);
            CP_COMMIT();
            if constexpr (!CPA) loadA((t + 1) * 32);
        }
        const int ab8 = (t & 1) * 8, ab = (t & 1) * 128, bb = (t & 1) * 32;
#pragma unroll
        for (int k8 = 0; k8 < 4; k8++) {
            const int kk8 = k8 * 8;
            uint32_t a[MT][4], b[NTT][2];
#pragma unroll
            for (int mt = 0; mt < MT; mt++) {
                if constexpr (CPA) {
                    int m0 = wm0 + mt * 16;
                    a[mt][0] = __float_as_uint(Asp[ab + m0 + qr][kk8 + qk]);
                    a[mt][1] = __float_as_uint(Asp[ab + m0 + qr + 8][kk8 + qk]);
                    a[mt][2] = __float_as_uint(Asp[ab + m0 + qr][kk8 + qk + 4]);
                    a[mt][3] = __float_as_uint(Asp[ab + m0 + qr + 8][kk8 + qk + 4]);
                } else {
                    float4 av = Ax[((ab8 + mtile0 + mt) * 4 + k8) * ACH + lane];
                    a[mt][0] = __float_as_uint(av.x);
                    a[mt][1] = __float_as_uint(av.y);
                    a[mt][2] = __float_as_uint(av.z);
                    a[mt][3] = __float_as_uint(av.w);
                }
            }
#pragma unroll
            for (int nt = 0; nt < NTT; nt++) {
                int n0 = wn0 + nt * 8;
                b[nt][0] = __float_as_uint(Bs[bb + kk8 + qk][n0 + qr]);
                b[nt][1] = __float_as_uint(Bs[bb + kk8 + qk + 4][n0 + qr]);
            }
#pragma unroll
            for (int mt = 0; mt < MT; mt++)
#pragma unroll
                for (int nt = 0; nt < NTT; nt++)
                    mma_tf32(c[mt][nt], a[mt], b[nt]);
        }
        if (t + 1 < nT) {
            if constexpr (!CPA) storeA((t + 1) & 1);
            CP_WAIT0();
        }
        __syncthreads();
    }

#pragma unroll
    for (int mt = 0; mt < MT; mt++) {
#pragma unroll
        for (int nt = 0; nt < NTT; nt++) {
            int row = row0 + wm0 + mt * 16 + qr;
            int col = wn0 + nt * 8 + 2 * qk;
            float2 lo = make_float2(c[mt][nt][0], c[mt][nt][1]);
            float2 hi = make_float2(c[mt][nt][2], c[mt][nt][3]);
            if (MODE == 0) {
                size_t off = (size_t)(bz * Hc + hy) * Sc * Pc;
                int cc = col & 63;
                if (col < 64) {   // g_k: raw (flash rounds after scaling)
                    *(float2*)(g_k + off + (size_t)row * Pc + cc) = lo;
                    *(float2*)(g_k + off + (size_t)(row + 8) * Pc + cc) = hi;
                } else {          // g_v: pre-round for cp.async consumers
                    lo.x = to_tf32(lo.x); lo.y = to_tf32(lo.y);
                    hi.x = to_tf32(hi.x); hi.y = to_tf32(hi.y);
                    *(float2*)(g_v + off + (size_t)row * Pc + cc) = lo;
                    *(float2*)(g_v + off + (size_t)(row + 8) * Pc + cc) = hi;
                }
            } else if (MODE == 1) {
                float* base = g_qv + (size_t)(bz * Hc + hy) * Sc * Pc;
                lo.x = to_tf32(lo.x); lo.y = to_tf32(lo.y);
                hi.x = to_tf32(hi.x); hi.y = to_tf32(hi.y);
                *(float2*)(base + (size_t)row * Pc + col) = lo;
                *(float2*)(base + (size_t)(row + 8) * Pc + col) = hi;
            } else {
                *(float2*)(Out + (size_t)row * Ec + n0g + col) = lo;
                *(float2*)(Out + (size_t)(row + 8) * Ec + n0g + col) = hi;
            }
        }
    }
}

constexpr int SMG128 = (AFL + 2 * 32 * 136) * (int)sizeof(float);
constexpr int SMG64  = (AFL + 2 * 32 * 72) * (int)sizeof(float);

// ---------------------------------------------------------------------------
// Flash attention, mma.sync tf32.  Q = k/sqrt(E) (regs), K = qv, V = v
// (cp.async double-buffered, pre-rounded at producers).  Ps in smem.
// Ks[2][128][68], Vs[2][128][72], Ps[128][132].  Output rounded to tf32.
// ---------------------------------------------------------------------------
constexpr int KSOFF = 2 * 128 * 68;
constexpr int VSOFF = KSOFF + 2 * 128 * 72;
constexpr int SMEM_FLASH = (VSOFF + 128 * 132) * (int)sizeof(float);

__global__ __launch_bounds__(256, 1)
void flash_mma() {
    extern __shared__ float smf[];
    float (*Ks)[68]  = (float(*)[68])smf;
    float (*Vs)[72]  = (float(*)[72])(smf + KSOFF);
    float (*Ps)[132] = (float(*)[132])(smf + VSOFF);
    const uint32_t ks_base = smem_u32(smf);
    const uint32_t vs_base = smem_u32(smf + KSOFF);

    const int i0 = (gridDim.x - 1 - blockIdx.x) * 128;  // heavy blocks first
    const int h = blockIdx.y, b = blockIdx.z;
    const int tid = threadIdx.x;
    const int wid = tid >> 5, lane = tid & 31;
    const int qk = lane & 3, qr = lane >> 2;
    const int m0 = wid * 16;

    const size_t base = (size_t)(b * Hc + h) * Sc * Pc;
    const float* kb  = g_k  + base;
    const float* qvb = g_qv + base;
    const float* vb  = g_v  + base;
    const float qscale = rsqrtf((float)Ec);

    // Q fragments in registers (one-time gmem gather, scaled + rounded)
    uint32_t qa[8][4];
    {
        const int r0g = i0 + m0 + qr, r1g = r0g + 8;
#pragma unroll
        for (int k8 = 0; k8 < 8; k8++) {
            int c0 = k8 * 8 + qk;
            qa[k8][0] = __float_as_uint(to_tf32(kb[(size_t)r0g * Pc + c0] * qscale));
            qa[k8][1] = __float_as_uint(to_tf32(kb[(size_t)r1g * Pc + c0] * qscale));
            qa[k8][2] = __float_as_uint(to_tf32(kb[(size_t)r0g * Pc + c0 + 4] * qscale));
            qa[k8][3] = __float_as_uint(to_tf32(kb[(size_t)r1g * Pc + c0 + 4] * qscale));
        }
    }

    auto fill = [&](int t) {
        const int buf = t & 1;
        const float* ksrc = qvb + (size_t)t * 128 * Pc;
        const float* vsrc = vb + (size_t)t * 128 * Pc;
#pragma unroll
        for (int j = 0; j < 8; j++) {
            int i = j * 256 + tid;          // 0..2047
            int r = i >> 4, c4 = (i & 15) * 4;
            cp_async16(ks_base + (uint32_t)(((buf * 128 + r) * 68 + c4) * 4),
                       ksrc + (size_t)r * Pc + c4);
            cp_async16(vs_base + (uint32_t)(((buf * 128 + r) * 72 + c4) * 4),
                       vsrc + (size_t)r * Pc + c4);
        }
        CP_COMMIT();
    };

    float mrow[2] = {-INFINITY, -INFINITY};
    float lrow[2] = {0.f, 0.f};
    float o[8][4];
#pragma unroll
    for (int nt = 0; nt < 8; nt++)
#pragma unroll
        for (int q = 0; q < 4; q++) o[nt][q] = 0.f;

    const int tN = i0 / 128 + 1;
    fill(0);

    for (int t = 0; t < tN; t++) {
        if (t + 1 < tN) fill(t + 1);
        if (t + 1 < tN)
            asm volatile("cp.async.wait_group 1;" ::: "memory");
        else
            asm volatile("cp.async.wait_group 0;" ::: "memory");
        __syncthreads();
        const int kbuf = (t & 1) * 128;

        // S = Q @ K^T : 16 n-frags, K=64
        float s[16][4];
#pragma unroll
        for (int nt = 0; nt < 16; nt++)
#pragma unroll
            for (int q = 0; q < 4; q++) s[nt][q] = 0.f;

#pragma unroll
        for (int k8 = 0; k8 < 8; k8++) {
            const int kk8 = k8 * 8;
#pragma unroll
            for (int nt = 0; nt < 16; nt++) {
                uint32_t bf[2];
                bf[0] = __float_as_uint(Ks[kbuf + nt * 8 + qr][kk8 + qk]);
                bf[1] = __float_as_uint(Ks[kbuf + nt * 8 + qr][kk8 + qk + 4]);
                mma_tf32(s[nt], qa[k8], bf);
            }
        }

        if (t == tN - 1) {  // diagonal block: causal mask (local indices)
            int r0 = m0 + qr, r1 = r0 + 8;
#pragma unroll
            for (int nt = 0; nt < 16; nt++) {
                int c0 = nt * 8 + 2 * qk;
                if (c0 > r0)     s[nt][0] = -INFINITY;
                if (c0 + 1 > r0) s[nt][1] = -INFINITY;
                if (c0 > r1)     s[nt][2] = -INFINITY;
                if (c0 + 1 > r1) s[nt][3] = -INFINITY;
            }
        }

        // online softmax (quad shuffles)
        float mx0 = mrow[0], mx1 = mrow[1];
#pragma unroll
        for (int nt = 0; nt < 16; nt++) {
            mx0 = fmaxf(mx0, fmaxf(s[nt][0], s[nt][1]));
            mx1 = fmaxf(mx1, fmaxf(s[nt][2], s[nt][3]));
        }
#pragma unroll
        for (int off = 1; off <= 2; off <<= 1) {
            mx0 = fmaxf(mx0, __shfl_xor_sync(0xffffffffu, mx0, off));
            mx1 = fmaxf(mx1, __shfl_xor_sync(0xffffffffu, mx1, off));
        }
        float alpha0 = __expf(mrow[0] - mx0);
        float alpha1 = __expf(mrow[1] - mx1);
        mrow[0] = mx0; mrow[1] = mx1;
        float sum0 = 0.f, sum1 = 0.f;
#pragma unroll
        for (int nt = 0; nt < 16; nt++) {
            int c0 = nt * 8 + 2 * qk;
            float p0 = to_tf32(__expf(s[nt][0] - mx0));
            float p1 = to_tf32(__expf(s[nt][1] - mx0));
            float p2 = to_tf32(__expf(s[nt][2] - mx1));
            float p3 = to_tf32(__expf(s[nt][3] - mx1));
            sum0 += p0 + p1;
            sum1 += p2 + p3;
            *(float2*)&Ps[m0 + qr][c0]     = make_float2(p0, p1);
            *(float2*)&Ps[m0 + qr + 8][c0] = make_float2(p2, p3);
        }
#pragma unroll
        for (int off = 1; off <= 2; off <<= 1) {
            sum0 += __shfl_xor_sync(0xffffffffu, sum0, off);
            sum1 += __shfl_xor_sync(0xffffffffu, sum1, off);
        }
        lrow[0] = lrow[0] * alpha0 + sum0;
        lrow[1] = lrow[1] * alpha1 + sum1;
#pragma unroll
        for (int nt = 0; nt < 8; nt++) {
            o[nt][0] *= alpha0; o[nt][1] *= alpha0;
            o[nt][2] *= alpha1; o[nt][3] *= alpha1;
        }
        __syncwarp();  // Ps rows are warp-private

        // O += P @ V : K=128, 8 n-frags
#pragma unroll
        for (int kk8 = 0; kk8 < 128; kk8 += 8) {
            uint32_t a[4];
            a[0] = __float_as_uint(Ps[m0 + qr][kk8 + qk]);
            a[1] = __float_as_uint(Ps[m0 + qr + 8][kk8 + qk]);
            a[2] = __float_as_uint(Ps[m0 + qr][kk8 + qk + 4]);
            a[3] = __float_as_uint(Ps[m0 + qr + 8][kk8 + qk + 4]);
#pragma unroll
            for (int nt = 0; nt < 8; nt++) {
                uint32_t bf[2];
                bf[0] = __float_as_uint(Vs[kbuf + kk8 + qk][nt * 8 + qr]);
                bf[1] = __float_as_uint(Vs[kbuf + kk8 + qk + 4][nt * 8 + qr]);
                mma_tf32(o[nt], a, bf);
            }
        }
        __syncthreads();  // all warps done with buf before it is refilled
    }

    float inv0 = 1.f / lrow[0], inv1 = 1.f / lrow[1];
    int r0 = i0 + m0 + qr, r1 = r0 + 8;
    float* d0 = g_attn + ((size_t)b * Sc + r0) * HPc + h * Pc;
    float* d1 = g_attn + ((size_t)b * Sc + r1) * HPc + h * Pc;
#pragma unroll
    for (int nt = 0; nt < 8; nt++) {
        int cc = nt * 8 + 2 * qk;
        // pre-round for lift's cp.async A path (same value lift's cvt produced)
        *(float2*)(d0 + cc) = make_float2(to_tf32(o[nt][0] * inv0),
                                          to_tf32(o[nt][1] * inv0));
        *(float2*)(d1 + cc) = make_float2(to_tf32(o[nt][2] * inv1),
                                          to_tf32(o[nt][3] * inv1));
    }
}

}  // namespace

extern "C" void kernel_launch(void* const* d_in, const int* in_sizes, int n_in,
                              void* d_out, int out_size) {
    (void)in_sizes; (void)n_in; (void)out_size;
    const float* x  = (const float*)d_in[0];   // (B,1,S,E)
    const float* kp = (const float*)d_in[1];   // (H,E,P)
    const float* vp = (const float*)d_in[2];   // (H,E,P)
    const float* qh = (const float*)d_in[3];   // (H,S,S)
    const float* lw = (const float*)d_in[4];   // (1,HP,E)
    float* out = (float*)d_out;                // (B,S,E)

    cudaFuncSetAttribute(mma_gemm<128, 0>,
                         cudaFuncAttributeMaxDynamicSharedMemorySize, SMG128);
    cudaFuncSetAttribute(mma_gemm<64, 1>,
                         cudaFuncAttributeMaxDynamicSharedMemorySize, SMG64);
    cudaFuncSetAttribute(mma_gemm<128, 2>,
                         cudaFuncAttributeMaxDynamicSharedMemorySize, SMG128);
    cudaFuncSetAttribute(flash_mma,
                         cudaFuncAttributeMaxDynamicSharedMemorySize, SMEM_FLASH);

    round_weights<<<(RW_N1 + RW_N2 + 255) / 256, 256>>>(kp, vp, lw);
    mma_gemm<128, 0><<<dim3(Sc / 128, Hc, Bc), 256, SMG128>>>(x, nullptr);
    mma_gemm<64, 1><<<dim3(Sc / 128, Hc, Bc), 256, SMG64>>>(qh, nullptr);
    flash_mma<<<dim3(Sc / 128, Hc, Bc), 256, SMEM_FLASH>>>();
    mma_gemm<128, 2><<<dim3(Bc * Sc / 128, Ec / 128), 256, SMG128>>>(nullptr, out);
}

// round 11
// speedup vs baseline: 3.7831x; 1.0069x over previous
#include <cuda_runtime.h>
#include <math.h>
#include <stdint.h>

namespace {

constexpr int Bc = 8, Sc = 1024, Ec = 768, Hc = 12, Pc = 64, HPc = 768;
constexpr int TILEF = 8192;   // floats per 128x64 fragment-order tile

__device__ float g_k[Bc * Hc * Sc * Pc];     // raw (flash scales+rounds)
__device__ float g_v[Bc * Hc * Sc * Pc];     // rounded, row-major (qv GEMM B)
__device__ float g_qvf[Bc * Hc * Sc * Pc];   // rounded, FRAG-ORDER (flash K)
__device__ float g_vf[Bc * Hc * Sc * Pc];    // rounded, FRAG-ORDER (flash V)
__device__ float g_attn[Bc * Sc * HPc];      // rounded (lift A via cp.async)
__device__ float g_wkv[Hc * Ec * 128];       // rounded kp||vp
__device__ float g_lw[HPc * Ec];             // rounded lifting

__device__ __forceinline__ float to_tf32(float x) {
    float y;
    asm("cvt.rna.tf32.f32 %0, %1;" : "=f"(y) : "f"(x));
    return y;
}

__device__ __forceinline__ void mma_tf32(float c[4], const uint32_t a[4],
                                         const uint32_t b[2]) {
    asm volatile(
        "mma.sync.aligned.m16n8k8.row.col.f32.tf32.tf32.f32 "
        "{%0,%1,%2,%3}, {%4,%5,%6,%7}, {%8,%9}, {%0,%1,%2,%3};"
        : "+f"(c[0]), "+f"(c[1]), "+f"(c[2]), "+f"(c[3])
        : "r"(a[0]), "r"(a[1]), "r"(a[2]), "r"(a[3]), "r"(b[0]), "r"(b[1]));
}

__device__ __forceinline__ uint32_t smem_u32(const void* p) {
    uint32_t a;
    asm("{ .reg .u64 t; cvta.to.shared.u64 t, %1; cvt.u32.u64 %0, t; }"
        : "=r"(a) : "l"(p));
    return a;
}
__device__ __forceinline__ void cp_async16(uint32_t dst, const void* src) {
    asm volatile("cp.async.cg.shared.global [%0], [%1], 16;"
                 :: "r"(dst), "l"(src) : "memory");
}
#define CP_COMMIT() asm volatile("cp.async.commit_group;" ::: "memory")
#define CP_WAIT0()  asm volatile("cp.async.wait_group 0;" ::: "memory")

// within-tile float index of value K[jl][p] in the QK-B fragment-order tile
__device__ __forceinline__ int kf_index(int jl, int p) {
    int np = jl >> 4, r8 = (jl >> 3) & 1, qr = jl & 7;
    int k8 = p >> 3, q7 = p & 7, qk = q7 & 3, half = q7 >> 2;
    return (((k8 * 8 + np) * 32 + qr * 4 + qk) << 2) + r8 * 2 + half;
}
// within-tile float index of value V[jl][p] in the PV-B fragment-order tile
__device__ __forceinline__ int vf_index(int jl, int p) {
    int kk8 = jl >> 3, j7 = jl & 7, qk = j7 & 3, halfj = j7 >> 2;
    int np = p >> 4, r8 = (p >> 3) & 1, qr = p & 7;
    return (((kk8 * 4 + np) * 32 + qr * 4 + qk) << 2) + r8 * 2 + halfj;
}

// ---------------------------------------------------------------------------
// Prologue: RNA-round the weights into scratch (enables cp.async B paths).
// ---------------------------------------------------------------------------
constexpr int RW_N1 = Hc * Ec * 128 / 4;
constexpr int RW_N2 = HPc * Ec / 4;

__global__ __launch_bounds__(256)
void round_weights(const float* __restrict__ kp, const float* __restrict__ vp,
                   const float* __restrict__ lw) {
    int idx = blockIdx.x * 256 + threadIdx.x;
    if (idx < RW_N1) {
        int n4 = (idx & 31) * 4;
        int e = (idx >> 5) % Ec;
        int h = idx / (32 * Ec);
        float4 v = (n4 < 64)
            ? *(const float4*)(kp + ((size_t)h * Ec + e) * Pc + n4)
            : *(const float4*)(vp + ((size_t)h * Ec + e) * Pc + (n4 - 64));
        v.x = to_tf32(v.x); v.y = to_tf32(v.y);
        v.z = to_tf32(v.z); v.w = to_tf32(v.w);
        ((float4*)g_wkv)[idx] = v;
    } else if (idx < RW_N1 + RW_N2) {
        int f = idx - RW_N1;
        float4 v = ((const float4*)lw)[f];
        v.x = to_tf32(v.x); v.y = to_tf32(v.y);
        v.z = to_tf32(v.z); v.w = to_tf32(v.w);
        ((float4*)g_lw)[f] = v;
    }
}

// ---------------------------------------------------------------------------
// tf32 mma.sync GEMM, double-buffered, k-step 32 (as R10).
// MODE 0: proj  MODE 1: qv (NT=64)  MODE 2: lift
// ---------------------------------------------------------------------------
constexpr int ACH = 33;
constexpr int AFL = 2 * 128 * 36;

template <int NT, int MODE>
__global__ __launch_bounds__(256, 2)
void mma_gemm(const float* __restrict__ P0, float* __restrict__ Out) {
    constexpr bool CPA = (MODE == 2);
    constexpr int WR = (NT == 128) ? 2 : 4;
    constexpr int WC = (NT == 128) ? 4 : 2;
    constexpr int WM = 128 / WR;
    constexpr int WN = NT / WC;
    constexpr int MT = WM / 16;
    constexpr int NTT = WN / 8;
    constexpr int BSTR = NT + 8;
    constexpr int NB4 = (32 * NT) / (4 * 256);

    extern __shared__ float smg[];
    float4* Ax = (float4*)smg;
    float (*Asp)[36] = (float(*)[36])smg;
    float (*Bs)[BSTR] = (float(*)[BSTR])(smg + AFL);
    const uint32_t as_base = smem_u32(smg);
    const uint32_t bs_base = smem_u32(smg + AFL);

    const int tid = threadIdx.x;
    const int wid = tid >> 5, lane = tid & 31;
    const int wr = (NT == 128) ? (wid >> 2) : (wid >> 1);
    const int wc = (NT == 128) ? (wid & 3) : (wid & 1);
    const int wm0 = wr * WM, wn0 = wc * WN;
    const int qk = lane & 3, qr = lane >> 2;
    const int mtile0 = wm0 >> 4;

    const int row0 = blockIdx.x * 128;
    const int hy = blockIdx.y, bz = blockIdx.z;

    const float* A;
    int lda, K;
    const float* Bg = nullptr;
    int ldb = 0;
    int n0g = 0;
    if (MODE == 0) {
        A = P0 + (size_t)bz * Sc * Ec; lda = Ec; K = Ec;
        Bg = g_wkv + (size_t)hy * Ec * 128; ldb = 128;
    } else if (MODE == 1) {
        A = P0 + (size_t)hy * Sc * Sc; lda = Sc; K = Sc;
        Bg = g_v + (size_t)(bz * Hc + hy) * Sc * Pc; ldb = Pc;
    } else {
        A = g_attn; lda = HPc; K = HPc;
        n0g = blockIdx.y * 128;
        Bg = g_lw + n0g; ldb = Ec;
    }

    float c[MT][NTT][4];
#pragma unroll
    for (int mt = 0; mt < MT; mt++)
#pragma unroll
        for (int nt = 0; nt < NTT; nt++)
#pragma unroll
            for (int q = 0; q < 4; q++) c[mt][nt][q] = 0.f;

    float4 pa[4];

    auto fillB = [&](int t) {
        const int k0 = t * 32, buf = t & 1;
#pragma unroll
        for (int j = 0; j < NB4; j++) {
            int i = j * 256 + tid;
            int kk = (NT == 128) ? (i >> 5) : (i >> 4);
            int n4 = (NT == 128) ? ((i & 31) * 4) : ((i & 15) * 4);
            cp_async16(bs_base + (uint32_t)(((buf * 32 + kk) * BSTR + n4) * 4),
                       Bg + (size_t)(k0 + kk) * ldb + n4);
        }
    };
    auto fillA_cp = [&](int t) {
        const int k0 = t * 32, buf = t & 1;
#pragma unroll
        for (int j = 0; j < 4; j++) {
            int i = j * 256 + tid;
            int m = i >> 3, e4 = (i & 7) * 4;
            cp_async16(as_base + (uint32_t)(((buf * 128 + m) * 36 + e4) * 4),
                       A + (size_t)(row0 + m) * lda + k0 + e4);
        }
    };
    auto loadA = [&](int k0) {
#pragma unroll
        for (int j = 0; j < 4; j++) {
            int i = j * 256 + tid;
            int m = i >> 3, e4 = (i & 7) * 4;
            pa[j] = *(const float4*)(A + (size_t)(row0 + m) * lda + k0 + e4);
        }
    };
    auto storeA = [&](int buf) {
#pragma unroll
        for (int j = 0; j < 4; j++) {
            int i = j * 256 + tid;
            int m = i >> 3, e4 = (i & 7) * 4;
            int mtile = m >> 4, k8 = e4 >> 3;
            int comp = ((m >> 3) & 1) | (((e4 >> 2) & 1) << 1);
            int lane0 = (m & 7) * 4;
            float* dst = smg + (((buf * 8 + mtile) * 4 + k8) * ACH + lane0) * 4 + comp;
            dst[0]  = to_tf32(pa[j].x);
            dst[4]  = to_tf32(pa[j].y);
            dst[8]  = to_tf32(pa[j].z);
            dst[12] = to_tf32(pa[j].w);
        }
    };

    fillB(0);
    if constexpr (CPA) fillA_cp(0);
    CP_COMMIT();
    if constexpr (!CPA) { loadA(0); storeA(0); }
    CP_WAIT0();
    __syncthreads();

    const int nT = K / 32;
    for (int t = 0; t < nT; t++) {
        if (t + 1 < nT) {
            fillB(t + 1);
            if constexpr (CPA) fillA_cp(t + 1);
            CP_COMMIT();
            if constexpr (!CPA) loadA((t + 1) * 32);
        }
        const int ab8 = (t & 1) * 8, ab = (t & 1) * 128, bb = (t & 1) * 32;
#pragma unroll
        for (int k8 = 0; k8 < 4; k8++) {
            const int kk8 = k8 * 8;
            uint32_t a[MT][4], b[NTT][2];
#pragma unroll
            for (int mt = 0; mt < MT; mt++) {
                if constexpr (CPA) {
                    int m0 = wm0 + mt * 16;
                    a[mt][0] = __float_as_uint(Asp[ab + m0 + qr][kk8 + qk]);
                    a[mt][1] = __float_as_uint(Asp[ab + m0 + qr + 8][kk8 + qk]);
                    a[mt][2] = __float_as_uint(Asp[ab + m0 + qr][kk8 + qk + 4]);
                    a[mt][3] = __float_as_uint(Asp[ab + m0 + qr + 8][kk8 + qk + 4]);
                } else {
                    float4 av = Ax[((ab8 + mtile0 + mt) * 4 + k8) * ACH + lane];
                    a[mt][0] = __float_as_uint(av.x);
                    a[mt][1] = __float_as_uint(av.y);
                    a[mt][2] = __float_as_uint(av.z);
                    a[mt][3] = __float_as_uint(av.w);
                }
            }
#pragma unroll
            for (int nt = 0; nt < NTT; nt++) {
                int n0 = wn0 + nt * 8;
                b[nt][0] = __float_as_uint(Bs[bb + kk8 + qk][n0 + qr]);
                b[nt][1] = __float_as_uint(Bs[bb + kk8 + qk + 4][n0 + qr]);
            }
#pragma unroll
            for (int mt = 0; mt < MT; mt++)
#pragma unroll
                for (int nt = 0; nt < NTT; nt++)
                    mma_tf32(c[mt][nt], a[mt], b[nt]);
        }
        if (t + 1 < nT) {
            if constexpr (!CPA) storeA((t + 1) & 1);
            CP_WAIT0();
        }
        __syncthreads();
    }

#pragma unroll
    for (int mt = 0; mt < MT; mt++) {
#pragma unroll
        for (int nt = 0; nt < NTT; nt++) {
            int row = row0 + wm0 + mt * 16 + qr;
            int col = wn0 + nt * 8 + 2 * qk;
            float2 lo = make_float2(c[mt][nt][0], c[mt][nt][1]);
            float2 hi = make_float2(c[mt][nt][2], c[mt][nt][3]);
            if (MODE == 0) {
                size_t off = (size_t)(bz * Hc + hy) * Sc * Pc;
                int cc = col & 63;
                if (col < 64) {   // g_k: raw (flash rounds after scaling)
                    *(float2*)(g_k + off + (size_t)row * Pc + cc) = lo;
                    *(float2*)(g_k + off + (size_t)(row + 8) * Pc + cc) = hi;
                } else {          // g_v rounded row-major + g_vf frag-order
                    lo.x = to_tf32(lo.x); lo.y = to_tf32(lo.y);
                    hi.x = to_tf32(hi.x); hi.y = to_tf32(hi.y);
                    *(float2*)(g_v + off + (size_t)row * Pc + cc) = lo;
                    *(float2*)(g_v + off + (size_t)(row + 8) * Pc + cc) = hi;
                    size_t tb = (((size_t)(bz * Hc + hy)) * 8 + (row >> 7)) * TILEF;
                    int jl = row & 127;
                    g_vf[tb + vf_index(jl, cc)]         = lo.x;
                    g_vf[tb + vf_index(jl, cc + 1)]     = lo.y;
                    g_vf[tb + vf_index(jl + 8, cc)]     = hi.x;
                    g_vf[tb + vf_index(jl + 8, cc + 1)] = hi.y;
                }
            } else if (MODE == 1) {   // g_qvf frag-order only
                size_t tb = (((size_t)(bz * Hc + hy)) * 8 + (row >> 7)) * TILEF;
                int jl = row & 127;
                g_qvf[tb + kf_index(jl, col)]         = to_tf32(lo.x);
                g_qvf[tb + kf_index(jl, col + 1)]     = to_tf32(lo.y);
                g_qvf[tb + kf_index(jl + 8, col)]     = to_tf32(hi.x);
                g_qvf[tb + kf_index(jl + 8, col + 1)] = to_tf32(hi.y);
            } else {
                *(float2*)(Out + (size_t)row * Ec + n0g + col) = lo;
                *(float2*)(Out + (size_t)(row + 8) * Ec + n0g + col) = hi;
            }
        }
    }
}

constexpr int SMG128 = (AFL + 2 * 32 * 136) * (int)sizeof(float);
constexpr int SMG64  = (AFL + 2 * 32 * 72) * (int)sizeof(float);

// ---------------------------------------------------------------------------
// Flash attention, mma.sync tf32.  Q = k/sqrt(E) (regs), K = g_qvf, V = g_vf
// (fragment-order gmem -> cp.async -> LDS.128 serves two MMAs).
// Smem: KF[2][8192], VF[2][8192], Ps[128][132].
// ---------------------------------------------------------------------------
constexpr int PSOFF = 4 * TILEF;
constexpr int SMEM_FLASH = (PSOFF + 128 * 132) * (int)sizeof(float);

__global__ __launch_bounds__(256, 1)
void flash_mma() {
    extern __shared__ float smf[];
    float (*Ps)[132] = (float(*)[132])(smf + PSOFF);
    const uint32_t ks_base = smem_u32(smf);
    const uint32_t vs_base = smem_u32(smf + 2 * TILEF);

    const int i0 = (gridDim.x - 1 - blockIdx.x) * 128;  // heavy blocks first
    const int h = blockIdx.y, b = blockIdx.z;
    const int tid = threadIdx.x;
    const int wid = tid >> 5, lane = tid & 31;
    const int qk = lane & 3, qr = lane >> 2;
    const int m0 = wid * 16;

    const int bh = b * Hc + h;
    const float* kb = g_k + (size_t)bh * Sc * Pc;
    const float* kfb = g_qvf + (size_t)bh * 8 * TILEF;
    const float* vfb = g_vf + (size_t)bh * 8 * TILEF;
    const float qscale = rsqrtf((float)Ec);

    // Q fragments in registers (one-time gmem gather, scaled + rounded)
    uint32_t qa[8][4];
    {
        const int r0g = i0 + m0 + qr, r1g = r0g + 8;
#pragma unroll
        for (int k8 = 0; k8 < 8; k8++) {
            int c0 = k8 * 8 + qk;
            qa[k8][0] = __float_as_uint(to_tf32(kb[(size_t)r0g * Pc + c0] * qscale));
            qa[k8][1] = __float_as_uint(to_tf32(kb[(size_t)r1g * Pc + c0] * qscale));
            qa[k8][2] = __float_as_uint(to_tf32(kb[(size_t)r0g * Pc + c0 + 4] * qscale));
            qa[k8][3] = __float_as_uint(to_tf32(kb[(size_t)r1g * Pc + c0 + 4] * qscale));
        }
    }

    auto fill = [&](int t) {
        const int buf = t & 1;
        const float* ksrc = kfb + (size_t)t * TILEF;
        const float* vsrc = vfb + (size_t)t * TILEF;
#pragma unroll
        for (int j = 0; j < 8; j++) {
            int i = (j * 256 + tid) * 4;        // float offset, 16B aligned
            cp_async16(ks_base + (uint32_t)((buf * TILEF + i) * 4), ksrc + i);
            cp_async16(vs_base + (uint32_t)((buf * TILEF + i) * 4), vsrc + i);
        }
        CP_COMMIT();
    };

    float mrow[2] = {-INFINITY, -INFINITY};
    float lrow[2] = {0.f, 0.f};
    float o[8][4];
#pragma unroll
    for (int nt = 0; nt < 8; nt++)
#pragma unroll
        for (int q = 0; q < 4; q++) o[nt][q] = 0.f;

    const int tN = i0 / 128 + 1;
    fill(0);

    for (int t = 0; t < tN; t++) {
        if (t + 1 < tN) fill(t + 1);
        if (t + 1 < tN)
            asm volatile("cp.async.wait_group 1;" ::: "memory");
        else
            asm volatile("cp.async.wait_group 0;" ::: "memory");
        __syncthreads();
        const float4* KF4 = (const float4*)smf + (t & 1) * (TILEF / 4);
        const float4* VF4 = (const float4*)(smf + 2 * TILEF) + (t & 1) * (TILEF / 4);

        // S = Q @ K^T : one LDS.128 per np feeds two mmas
        float s[16][4];
#pragma unroll
        for (int nt = 0; nt < 16; nt++)
#pragma unroll
            for (int q = 0; q < 4; q++) s[nt][q] = 0.f;

#pragma unroll
        for (int k8 = 0; k8 < 8; k8++) {
            const int base = k8 * 256 + lane;
#pragma unroll
            for (int np = 0; np < 8; np++) {
                float4 bb = KF4[base + np * 32];
                uint32_t b01[2] = {__float_as_uint(bb.x), __float_as_uint(bb.y)};
                uint32_t b23[2] = {__float_as_uint(bb.z), __float_as_uint(bb.w)};
                mma_tf32(s[2 * np], qa[k8], b01);
                mma_tf32(s[2 * np + 1], qa[k8], b23);
            }
        }

        if (t == tN - 1) {  // diagonal block: causal mask (local indices)
            int r0 = m0 + qr, r1 = r0 + 8;
#pragma unroll
            for (int nt = 0; nt < 16; nt++) {
                int c0 = nt * 8 + 2 * qk;
                if (c0 > r0)     s[nt][0] = -INFINITY;
                if (c0 + 1 > r0) s[nt][1] = -INFINITY;
                if (c0 > r1)     s[nt][2] = -INFINITY;
                if (c0 + 1 > r1) s[nt][3] = -INFINITY;
            }
        }

        // online softmax (quad shuffles)
        float mx0 = mrow[0], mx1 = mrow[1];
#pragma unroll
        for (int nt = 0; nt < 16; nt++) {
            mx0 = fmaxf(mx0, fmaxf(s[nt][0], s[nt][1]));
            mx1 = fmaxf(mx1, fmaxf(s[nt][2], s[nt][3]));
        }
#pragma unroll
        for (int off = 1; off <= 2; off <<= 1) {
            mx0 = fmaxf(mx0, __shfl_xor_sync(0xffffffffu, mx0, off));
            mx1 = fmaxf(mx1, __shfl_xor_sync(0xffffffffu, mx1, off));
        }
        float alpha0 = __expf(mrow[0] - mx0);
        float alpha1 = __expf(mrow[1] - mx1);
        mrow[0] = mx0; mrow[1] = mx1;
        float sum0 = 0.f, sum1 = 0.f;
#pragma unroll
        for (int nt = 0; nt < 16; nt++) {
            int c0 = nt * 8 + 2 * qk;
            float p0 = to_tf32(__expf(s[nt][0] - mx0));
            float p1 = to_tf32(__expf(s[nt][1] - mx0));
            float p2 = to_tf32(__expf(s[nt][2] - mx1));
            float p3 = to_tf32(__expf(s[nt][3] - mx1));
            sum0 += p0 + p1;
            sum1 += p2 + p3;
            *(float2*)&Ps[m0 + qr][c0]     = make_float2(p0, p1);
            *(float2*)&Ps[m0 + qr + 8][c0] = make_float2(p2, p3);
        }
#pragma unroll
        for (int off = 1; off <= 2; off <<= 1) {
            sum0 += __shfl_xor_sync(0xffffffffu, sum0, off);
            sum1 += __shfl_xor_sync(0xffffffffu, sum1, off);
        }
        lrow[0] = lrow[0] * alpha0 + sum0;
        lrow[1] = lrow[1] * alpha1 + sum1;
#pragma unroll
        for (int nt = 0; nt < 8; nt++) {
            o[nt][0] *= alpha0; o[nt][1] *= alpha0;
            o[nt][2] *= alpha1; o[nt][3] *= alpha1;
        }
        __syncwarp();  // Ps rows are warp-private

        // O += P @ V : one LDS.128 per np feeds two mmas
#pragma unroll
        for (int kk8 = 0; kk8 < 16; kk8++) {
            const int kc = kk8 * 8;
            uint32_t a[4];
            a[0] = __float_as_uint(Ps[m0 + qr][kc + qk]);
            a[1] = __float_as_uint(Ps[m0 + qr + 8][kc + qk]);
            a[2] = __float_as_uint(Ps[m0 + qr][kc + qk + 4]);
            a[3] = __float_as_uint(Ps[m0 + qr + 8][kc + qk + 4]);
#pragma unroll
            for (int np = 0; np < 4; np++) {
                float4 bb = VF4[(kk8 * 4 + np) * 32 + lane];
                uint32_t b01[2] = {__float_as_uint(bb.x), __float_as_uint(bb.y)};
                uint32_t b23[2] = {__float_as_uint(bb.z), __float_as_uint(bb.w)};
                mma_tf32(o[2 * np], a, b01);
                mma_tf32(o[2 * np + 1], a, b23);
            }
        }
        __syncthreads();  // all warps done with buf before it is refilled
    }

    float inv0 = 1.f / lrow[0], inv1 = 1.f / lrow[1];
    int r0 = i0 + m0 + qr, r1 = r0 + 8;
    float* d0 = g_attn + ((size_t)b * Sc + r0) * HPc + h * Pc;
    float* d1 = g_attn + ((size_t)b * Sc + r1) * HPc + h * Pc;
#pragma unroll
    for (int nt = 0; nt < 8; nt++) {
        int cc = nt * 8 + 2 * qk;
        *(float2*)(d0 + cc) = make_float2(to_tf32(o[nt][0] * inv0),
                                          to_tf32(o[nt][1] * inv0));
        *(float2*)(d1 + cc) = make_float2(to_tf32(o[nt][2] * inv1),
                                          to_tf32(o[nt][3] * inv1));
    }
}

}  // namespace

extern "C" void kernel_launch(void* const* d_in, const int* in_sizes, int n_in,
                              void* d_out, int out_size) {
    (void)in_sizes; (void)n_in; (void)out_size;
    const float* x  = (const float*)d_in[0];   // (B,1,S,E)
    const float* kp = (const float*)d_in[1];   // (H,E,P)
    const float* vp = (const float*)d_in[2];   // (H,E,P)
    const float* qh = (const float*)d_in[3];   // (H,S,S)
    const float* lw = (const float*)d_in[4];   // (1,HP,E)
    float* out = (float*)d_out;                // (B,S,E)

    cudaFuncSetAttribute(mma_gemm<128, 0>,
                         cudaFuncAttributeMaxDynamicSharedMemorySize, SMG128);
    cudaFuncSetAttribute(mma_gemm<64, 1>,
                         cudaFuncAttributeMaxDynamicSharedMemorySize, SMG64);
    cudaFuncSetAttribute(mma_gemm<128, 2>,
                         cudaFuncAttributeMaxDynamicSharedMemorySize, SMG128);
    cudaFuncSetAttribute(flash_mma,
                         cudaFuncAttributeMaxDynamicSharedMemorySize, SMEM_FLASH);

    round_weights<<<(RW_N1 + RW_N2 + 255) / 256, 256>>>(kp, vp, lw);
    mma_gemm<128, 0><<<dim3(Sc / 128, Hc, Bc), 256, SMG128>>>(x, nullptr);
    mma_gemm<64, 1><<<dim3(Sc / 128, Hc, Bc), 256, SMG64>>>(qh, nullptr);
    flash_mma<<<dim3(Sc / 128, Hc, Bc), 256, SMEM_FLASH>>>();
    mma_gemm<128, 2><<<dim3(Bc * Sc / 128, Ec / 128), 256, SMG128>>>(nullptr, out);
}